// round 6
// baseline (speedup 1.0000x reference)
#include <cuda_runtime.h>
#include <cstdint>

// Problem constants
#define BB 128
#define TT 256
#define CC 384
#define HH 6
#define DD 64
#define NTOK (BB * TT)   // 32768

// Scratch (static device globals — no dynamic allocation allowed)
__device__ float g_q[NTOK * CC];       // [b*T+t][h*64+d]
__device__ float g_k[NTOK * CC];
__device__ float g_v[NTOK * CC];
__device__ float g_attn[NTOK * CC];    // [b*T + t][h*D + d]
__device__ float g_wqT[CC * CC];       // [n=h*64+d][k=c]  K-major
__device__ float g_wkT[CC * CC];
__device__ float g_wvT[CC * CC];
__device__ float g_wpT[CC * CC];       // [n][k]

// ---------------------------------------------------------------------------
__device__ __forceinline__ float tf32r(float x) {
    uint32_t o;
    asm("cvt.rna.tf32.f32 %0, %1;" : "=r"(o) : "f"(x));
    return __uint_as_float(o);
}

__device__ __forceinline__ void mma_tf32(float* c, const uint32_t* a,
                                         const uint32_t* b) {
    asm volatile(
        "mma.sync.aligned.m16n8k8.row.col.f32.tf32.tf32.f32 "
        "{%0,%1,%2,%3}, {%4,%5,%6,%7}, {%8,%9}, {%0,%1,%2,%3};"
        : "+f"(c[0]), "+f"(c[1]), "+f"(c[2]), "+f"(c[3])
        : "r"(a[0]), "r"(a[1]), "r"(a[2]), "r"(a[3]), "r"(b[0]), "r"(b[1]));
}

// ===========================================================================
// Weight transpose: produce K-major B operands.
// ===========================================================================
__global__ void transpose_w(const float* __restrict__ wq, const float* __restrict__ wk,
                            const float* __restrict__ wv, const float* __restrict__ wp,
                            float* __restrict__ qT, float* __restrict__ kT,
                            float* __restrict__ vT, float* __restrict__ pT)
{
    int idx = blockIdx.x * 256 + threadIdx.x;
    if (idx >= CC * CC) return;
    int n = idx / CC, k = idx - n * CC;
    int h = n >> 6, d = n & 63;
    int src = (h * CC + k) * DD + d;
    qT[idx] = wq[src];
    kT[idx] = wk[src];
    vT[idx] = wv[src];
    pT[idx] = wp[k * CC + n];
}

// ===========================================================================
// Tensor-core tf32 GEMM, fragment-packed SMEM.
//   C[m][n] = sum_k A[m][k]*Bt[n][k] (+bias)
//   CTA 128x128, 8 warps (2m x 4n), warp tile 64x32, K-chunk 32, 2 stages.
//   SMEM A stage: [mtile8][ks4][128f]  — float4 idx (lane^ks) holds a0..a3
//   SMEM B stage: [ntile16][kp2][128f] — float4 idx (lane^kp) holds
//                                        {b0,b1 of even ks, b0,b1 of odd ks}
// ===========================================================================
#define KTILE 32
#define NCHUNK (CC / KTILE)     // 12
#define STGF 4096               // floats per operand stage
#define GEMM_SMEM (4 * STGF * (int)sizeof(float))   // 64 KB

__device__ __forceinline__ void gemm_core(
    const float* __restrict__ A, const float* __restrict__ Bt,
    const float* __restrict__ bias, float* __restrict__ Cout,
    int m0, int n0, float* sm)
{
    const int tid = threadIdx.x;
    const int wid = tid >> 5, lane = tid & 31;
    const int gid = lane >> 2, tig = lane & 3;
    const int warp_m = wid & 1;
    const int warp_n = wid >> 1;

    // ---- loader constants (chunk-invariant) ----
    const int q    = tid & 7;        // col-quad within row
    const int ksl  = q >> 1;         // ks of this quad
    const int kpl  = q >> 2;         // ks-pair
    const int rowi[4] = { (tid +   0) >> 3, (tid + 256) >> 3,
                          (tid + 512) >> 3, (tid + 768) >> 3 };
    // destination base offsets (element j adds the XOR'd lane term)
    int dstA[4], dstB[4];
#pragma unroll
    for (int i = 0; i < 4; i++) {
        const int r = rowi[i];
        dstA[i] = (((r >> 4) << 2) + ksl) * 128 + 2 * (q & 1) + ((r >> 3) & 1);
        dstB[i] = (((r >> 3) << 1) + kpl) * 128 + (q & 3);
    }

    float acc[4][4][4];
#pragma unroll
    for (int i = 0; i < 4; i++)
#pragma unroll
        for (int j = 0; j < 4; j++)
#pragma unroll
            for (int r = 0; r < 4; r++) acc[i][j][r] = 0.0f;

    const int lc = q * 4;
    const float* Ap  = A  + (long)m0 * CC + lc;
    const float* Btp = Bt + (long)n0 * CC + lc;

    float4 ra[4], rb[4];
#pragma unroll
    for (int i = 0; i < 4; i++) {
        ra[i] = *(const float4*)(Ap  + (long)rowi[i] * CC);
        rb[i] = *(const float4*)(Btp + (long)rowi[i] * CC);
    }

    // scatter-store one operand pair into stage s
    auto store_stage = [&](int s) {
        float* as = sm + s * STGF;
        float* bs = sm + 2 * STGF + s * STGF;
#pragma unroll
        for (int i = 0; i < 4; i++) {
            const int la = (rowi[i] & 7) * 4;   // lane_dst base
            const float av[4] = { ra[i].x, ra[i].y, ra[i].z, ra[i].w };
            const float bv[4] = { rb[i].x, rb[i].y, rb[i].z, rb[i].w };
#pragma unroll
            for (int j = 0; j < 4; j++) {
                as[dstA[i] + (((la + j) ^ ksl) << 2)] = tf32r(av[j]);
                bs[dstB[i] + (((la + j) ^ kpl) << 2)] = tf32r(bv[j]);
            }
        }
    };

    store_stage(0);
    __syncthreads();

    for (int c = 0; c < NCHUNK; c++) {
        const int s = c & 1;
        const bool more = (c + 1 < NCHUNK);
        if (more) {
            const int k0 = (c + 1) * KTILE;
#pragma unroll
            for (int i = 0; i < 4; i++) {
                ra[i] = *(const float4*)(Ap  + (long)rowi[i] * CC + k0);
                rb[i] = *(const float4*)(Btp + (long)rowi[i] * CC + k0);
            }
        }

        const float* As = sm + s * STGF;
        const float* Bs = sm + 2 * STGF + s * STGF;

#pragma unroll
        for (int kp = 0; kp < 2; kp++) {
            uint4 bfv[4];
#pragma unroll
            for (int nt = 0; nt < 4; nt++)
                bfv[nt] = *(const uint4*)(Bs +
                    (((warp_n * 4 + nt) * 2 + kp) * 128) + ((lane ^ kp) << 2));
#pragma unroll
            for (int hf = 0; hf < 2; hf++) {
                const int ks = kp * 2 + hf;
                uint4 afv[4];
#pragma unroll
                for (int mt = 0; mt < 4; mt++)
                    afv[mt] = *(const uint4*)(As +
                        (((warp_m * 4 + mt) * 4 + ks) * 128) + ((lane ^ ks) << 2));
#pragma unroll
                for (int mt = 0; mt < 4; mt++) {
#pragma unroll
                    for (int nt = 0; nt < 4; nt++) {
                        uint32_t b2[2];
                        if (hf == 0) { b2[0] = bfv[nt].x; b2[1] = bfv[nt].y; }
                        else         { b2[0] = bfv[nt].z; b2[1] = bfv[nt].w; }
                        mma_tf32(acc[mt][nt], (const uint32_t*)&afv[mt], b2);
                    }
                }
            }
        }

        if (more) {
            __syncthreads();        // stage s^1 fully consumed (prev chunk)
            store_stage(s ^ 1);
            __syncthreads();
        }
    }

    // Epilogue (fragment layout unchanged)
#pragma unroll
    for (int mt = 0; mt < 4; mt++) {
#pragma unroll
        for (int nt = 0; nt < 4; nt++) {
            const int n = n0 + warp_n * 32 + nt * 8 + 2 * tig;
            float bx = 0.0f, by = 0.0f;
            if (bias) { bx = bias[n]; by = bias[n + 1]; }
            const long mA = m0 + warp_m * 64 + mt * 16 + gid;
            float2 v0 = make_float2(acc[mt][nt][0] + bx, acc[mt][nt][1] + by);
            float2 v1 = make_float2(acc[mt][nt][2] + bx, acc[mt][nt][3] + by);
            *(float2*)(Cout + mA * CC + n)       = v0;
            *(float2*)(Cout + (mA + 8) * CC + n) = v1;
        }
    }
}

// Output-projection GEMM (single B matrix, with bias)
__global__ __launch_bounds__(256, 2) void gemm_mma(
    const float* __restrict__ A, const float* __restrict__ Bt,
    const float* __restrict__ bias, float* __restrict__ Cout)
{
    extern __shared__ __align__(16) float sm[];
    gemm_core(A, Bt, bias, Cout, blockIdx.x * 128, blockIdx.y * 128, sm);
}

// Fused QKV GEMM: grid.y in [0,9): matrix = y/3, n0 = (y%3)*128
__global__ __launch_bounds__(256, 2) void gemm_qkv(
    const float* __restrict__ X,
    const float* __restrict__ wqT, const float* __restrict__ wkT,
    const float* __restrict__ wvT,
    float* __restrict__ qO, float* __restrict__ kO, float* __restrict__ vO)
{
    extern __shared__ __align__(16) float sm[];
    const int mat = blockIdx.y / 3;
    const int n0  = (blockIdx.y % 3) * 128;
    const float* Bt = (mat == 0) ? wqT : (mat == 1) ? wkT : wvT;
    float* Cout     = (mat == 0) ? qO  : (mat == 1) ? kO  : vO;
    gemm_core(X, Bt, nullptr, Cout, blockIdx.x * 128, n0, sm);
}

// ===========================================================================
// Tensor-core causal flash attention (unchanged from round 5 — passing).
//   grid = (T/64, H, B), block = 128 (4 warps, 16 query rows each).
// ===========================================================================
#define ASTR 68
#define ATILE (64 * ASTR)
#define ATTN_SMEM (4 * ATILE * (int)sizeof(float))

__global__ __launch_bounds__(128) void attn_mma(
    const float* __restrict__ Q, const float* __restrict__ K,
    const float* __restrict__ V, float* __restrict__ O)
{
    extern __shared__ __align__(16) float sm[];
    float* Qs = sm;
    float* Ks = sm + ATILE;
    float* Vt = sm + 2 * ATILE;
    float* Ps = sm + 3 * ATILE;

    const int qb  = blockIdx.x;
    const int h   = blockIdx.y;
    const int b   = blockIdx.z;
    const int tid = threadIdx.x;
    const int wid = tid >> 5, lane = tid & 31;
    const int gid = lane >> 2, tig = lane & 3;
    const int mrow = wid * 16 + gid;

    const long qbase = ((long)(b * TT + qb * 64)) * CC + h * DD;

#pragma unroll
    for (int it = 0; it < 8; it++) {
        const int f = it * 128 + tid;
        const int r = f >> 4, d = (f & 15) * 4;
        float4 v = *(const float4*)(Q + qbase + (long)r * CC + d);
        float* qs = Qs + r * ASTR + d;
        qs[0] = tf32r(v.x); qs[1] = tf32r(v.y);
        qs[2] = tf32r(v.z); qs[3] = tf32r(v.w);
    }

    float o[8][4];
#pragma unroll
    for (int nt = 0; nt < 8; nt++)
#pragma unroll
        for (int r = 0; r < 4; r++) o[nt][r] = 0.0f;
    float m0 = -1e30f, m8 = -1e30f, l0 = 0.0f, l8 = 0.0f;

    __syncthreads();

    for (int kb = 0; kb <= qb; kb++) {
        const long kbase = ((long)(b * TT + kb * 64)) * CC + h * DD;

#pragma unroll
        for (int it = 0; it < 8; it++) {
            const int f = it * 128 + tid;
            const int r = f >> 4, d = (f & 15) * 4;
            float4 kv = *(const float4*)(K + kbase + (long)r * CC + d);
            float* ks = Ks + r * ASTR + d;
            ks[0] = tf32r(kv.x); ks[1] = tf32r(kv.y);
            ks[2] = tf32r(kv.z); ks[3] = tf32r(kv.w);
            float4 vv = *(const float4*)(V + kbase + (long)r * CC + d);
            Vt[(d + 0) * ASTR + r] = tf32r(vv.x);
            Vt[(d + 1) * ASTR + r] = tf32r(vv.y);
            Vt[(d + 2) * ASTR + r] = tf32r(vv.z);
            Vt[(d + 3) * ASTR + r] = tf32r(vv.w);
        }
        __syncthreads();

        float s[8][4];
#pragma unroll
        for (int nt = 0; nt < 8; nt++)
#pragma unroll
            for (int r = 0; r < 4; r++) s[nt][r] = 0.0f;

        const uint32_t* Qu = (const uint32_t*)Qs;
        const uint32_t* Ku = (const uint32_t*)Ks;
#pragma unroll
        for (int ks = 0; ks < 8; ks++) {
            uint32_t af[4];
            const int col = ks * 8 + tig;
            af[0] = Qu[mrow * ASTR + col];
            af[1] = Qu[(mrow + 8) * ASTR + col];
            af[2] = Qu[mrow * ASTR + col + 4];
            af[3] = Qu[(mrow + 8) * ASTR + col + 4];
#pragma unroll
            for (int nt = 0; nt < 8; nt++) {
                uint32_t bf[2];
                bf[0] = Ku[(nt * 8 + gid) * ASTR + col];
                bf[1] = Ku[(nt * 8 + gid) * ASTR + col + 4];
                mma_tf32(s[nt], af, bf);
            }
        }

        const bool diag = (kb == qb);
        const float scale = 0.125f;
        float rmax0 = -1e30f, rmax8 = -1e30f;
#pragma unroll
        for (int nt = 0; nt < 8; nt++) {
            const int c0 = nt * 8 + 2 * tig;
#pragma unroll
            for (int r = 0; r < 4; r++) {
                const int col = c0 + (r & 1);
                const int row = mrow + ((r >> 1) << 3);
                float v = s[nt][r] * scale;
                if (diag && col > row) v = -1e30f;
                s[nt][r] = v;
                if (r < 2) rmax0 = fmaxf(rmax0, v);
                else       rmax8 = fmaxf(rmax8, v);
            }
        }
        rmax0 = fmaxf(rmax0, __shfl_xor_sync(0xffffffffu, rmax0, 1));
        rmax0 = fmaxf(rmax0, __shfl_xor_sync(0xffffffffu, rmax0, 2));
        rmax8 = fmaxf(rmax8, __shfl_xor_sync(0xffffffffu, rmax8, 1));
        rmax8 = fmaxf(rmax8, __shfl_xor_sync(0xffffffffu, rmax8, 2));

        const float mn0 = fmaxf(m0, rmax0);
        const float mn8 = fmaxf(m8, rmax8);
        const float corr0 = __expf(m0 - mn0);
        const float corr8 = __expf(m8 - mn8);
        m0 = mn0; m8 = mn8;

        float ls0 = 0.0f, ls8 = 0.0f;
#pragma unroll
        for (int nt = 0; nt < 8; nt++) {
            float p0 = __expf(s[nt][0] - mn0);
            float p1 = __expf(s[nt][1] - mn0);
            float p2 = __expf(s[nt][2] - mn8);
            float p3 = __expf(s[nt][3] - mn8);
            s[nt][0] = p0; s[nt][1] = p1; s[nt][2] = p2; s[nt][3] = p3;
            ls0 += p0 + p1;
            ls8 += p2 + p3;
        }
        ls0 += __shfl_xor_sync(0xffffffffu, ls0, 1);
        ls0 += __shfl_xor_sync(0xffffffffu, ls0, 2);
        ls8 += __shfl_xor_sync(0xffffffffu, ls8, 1);
        ls8 += __shfl_xor_sync(0xffffffffu, ls8, 2);

        l0 = l0 * corr0 + ls0;
        l8 = l8 * corr8 + ls8;
#pragma unroll
        for (int nt = 0; nt < 8; nt++) {
            o[nt][0] *= corr0; o[nt][1] *= corr0;
            o[nt][2] *= corr8; o[nt][3] *= corr8;
        }

#pragma unroll
        for (int nt = 0; nt < 8; nt++) {
            float* p0 = Ps + mrow * ASTR + nt * 8 + 2 * tig;
            p0[0]            = tf32r(s[nt][0]);
            p0[1]            = tf32r(s[nt][1]);
            p0[8 * ASTR + 0] = tf32r(s[nt][2]);
            p0[8 * ASTR + 1] = tf32r(s[nt][3]);
        }
        __syncwarp();

        const uint32_t* Pu = (const uint32_t*)Ps;
        const uint32_t* Vu = (const uint32_t*)Vt;
#pragma unroll
        for (int ks = 0; ks < 8; ks++) {
            uint32_t af[4];
            const int col = ks * 8 + tig;
            af[0] = Pu[mrow * ASTR + col];
            af[1] = Pu[(mrow + 8) * ASTR + col];
            af[2] = Pu[mrow * ASTR + col + 4];
            af[3] = Pu[(mrow + 8) * ASTR + col + 4];
#pragma unroll
            for (int nt = 0; nt < 8; nt++) {
                uint32_t bf[2];
                bf[0] = Vu[(nt * 8 + gid) * ASTR + col];
                bf[1] = Vu[(nt * 8 + gid) * ASTR + col + 4];
                mma_tf32(o[nt], af, bf);
            }
        }
        __syncthreads();
    }

    const float inv0 = 1.0f / l0;
    const float inv8 = 1.0f / l8;
    const long orow0 = (long)(b * TT + qb * 64 + mrow) * CC + h * DD;
#pragma unroll
    for (int nt = 0; nt < 8; nt++) {
        const int col = nt * 8 + 2 * tig;
        *(float2*)(O + orow0 + col) =
            make_float2(o[nt][0] * inv0, o[nt][1] * inv0);
        *(float2*)(O + orow0 + 8 * CC + col) =
            make_float2(o[nt][2] * inv8, o[nt][3] * inv8);
    }
}

// ===========================================================================
extern "C" void kernel_launch(void* const* d_in, const int* in_sizes, int n_in,
                              void* d_out, int out_size)
{
    const float* x  = (const float*)d_in[0];
    const float* wq = (const float*)d_in[1];
    const float* wk = (const float*)d_in[2];
    const float* wv = (const float*)d_in[3];
    const float* wp = (const float*)d_in[4];
    const float* bp = (const float*)d_in[5];
    float* out = (float*)d_out;

    float *qp, *kp, *vp, *ap, *wqT, *wkT, *wvT, *wpT;
    cudaGetSymbolAddress((void**)&qp,  g_q);
    cudaGetSymbolAddress((void**)&kp,  g_k);
    cudaGetSymbolAddress((void**)&vp,  g_v);
    cudaGetSymbolAddress((void**)&ap,  g_attn);
    cudaGetSymbolAddress((void**)&wqT, g_wqT);
    cudaGetSymbolAddress((void**)&wkT, g_wkT);
    cudaGetSymbolAddress((void**)&wvT, g_wvT);
    cudaGetSymbolAddress((void**)&wpT, g_wpT);

    transpose_w<<<(CC * CC + 255) / 256, 256>>>(wq, wk, wv, wp, wqT, wkT, wvT, wpT);

    cudaFuncSetAttribute(gemm_qkv,
                         cudaFuncAttributeMaxDynamicSharedMemorySize, GEMM_SMEM);
    cudaFuncSetAttribute(gemm_mma,
                         cudaFuncAttributeMaxDynamicSharedMemorySize, GEMM_SMEM);
    gemm_qkv<<<dim3(NTOK / 128, 9), 256, GEMM_SMEM>>>(x, wqT, wkT, wvT, qp, kp, vp);

    cudaFuncSetAttribute(attn_mma,
                         cudaFuncAttributeMaxDynamicSharedMemorySize, ATTN_SMEM);
    attn_mma<<<dim3(TT / 64, HH, BB), 128, ATTN_SMEM>>>(qp, kp, vp, ap);

    gemm_mma<<<dim3(NTOK / 128, CC / 128), 256, GEMM_SMEM>>>(ap, wpT, bp, out);
}

// round 8
// speedup vs baseline: 1.3207x; 1.3207x over previous
#include <cuda_runtime.h>
#include <cstdint>

// Problem constants
#define BB 128
#define TT 256
#define CC 384
#define HH 6
#define DD 64
#define NTOK (BB * TT)   // 32768
#define KTILE 32
#define NCHUNK (CC / KTILE)     // 12

// Scratch (static device globals — no dynamic allocation allowed)
__device__ float g_xf[NTOK * CC];      // x, fragment-packed A operand
__device__ float g_q[NTOK * CC];       // row-major [tok][h*64+d]
__device__ float g_k[NTOK * CC];
__device__ float g_v[NTOK * CC];
__device__ float g_attn[NTOK * CC];    // fragment-packed A operand
__device__ float g_wqT[CC * CC];       // fragment-packed B operands
__device__ float g_wkT[CC * CC];
__device__ float g_wvT[CC * CC];
__device__ float g_wpT[CC * CC];

// ---------------------------------------------------------------------------
__device__ __forceinline__ float tf32r(float x) {
    uint32_t o;
    asm("cvt.rna.tf32.f32 %0, %1;" : "=r"(o) : "f"(x));
    return __uint_as_float(o);
}

__device__ __forceinline__ void mma_tf32(float* c, const uint32_t* a,
                                         const uint32_t* b) {
    asm volatile(
        "mma.sync.aligned.m16n8k8.row.col.f32.tf32.tf32.f32 "
        "{%0,%1,%2,%3}, {%4,%5,%6,%7}, {%8,%9}, {%0,%1,%2,%3};"
        : "+f"(c[0]), "+f"(c[1]), "+f"(c[2]), "+f"(c[3])
        : "r"(a[0]), "r"(a[1]), "r"(a[2]), "r"(a[3]), "r"(b[0]), "r"(b[1]));
}

__device__ __forceinline__ uint32_t smem_u32(const void* p) {
    uint32_t a;
    asm("{ .reg .u64 t; cvta.to.shared.u64 t, %1; cvt.u32.u64 %0, t; }"
        : "=r"(a) : "l"(p));
    return a;
}

__device__ __forceinline__ void cp16(uint32_t dst, const void* src) {
    asm volatile("cp.async.cg.shared.global [%0], [%1], 16;"
                 :: "r"(dst), "l"(src));
}
#define CP_COMMIT() asm volatile("cp.async.commit_group;" ::: "memory")
#define CP_WAIT2()  asm volatile("cp.async.wait_group 2;" ::: "memory")

// Fragment-packed layouts (per 128x32 block of 4096 floats):
//  A block: [mt(8)][ks(4)][lane(32)*4+j] ; element (m,k):
//    lane = (m&7)*4 + (k&3), j = ((m>>3)&1) + 2*((k>>2)&1)
__device__ __forceinline__ int afrag_off(int m, int k) {
    return (((m >> 7) * NCHUNK + (k >> 5)) << 12)
         + (((((m >> 4) & 7) << 2) + ((k >> 3) & 3)) << 7)
         + ((((m & 7) << 2) + (k & 3)) << 2)
         + ((m >> 3) & 1) + (((k >> 2) & 1) << 1);
}
//  B block: [nt(16)][kp(2)][lane(32)*4+j] ; element (n,k):
//    lane = (n&7)*4 + (k&3), j = ((k>>3)&1)*2 + ((k>>2)&1)
__device__ __forceinline__ int bfrag_off(int n, int k) {
    return (((n >> 7) * NCHUNK + (k >> 5)) << 12)
         + (((((n >> 3) & 15) << 1) + ((k >> 4) & 1)) << 7)
         + ((((n & 7) << 2) + (k & 3)) << 2)
         + (((k >> 3) & 1) << 1) + ((k >> 2) & 1);
}

// ===========================================================================
// Pack x into fragment-order A operand (tf32-rounded).
// ===========================================================================
__global__ __launch_bounds__(256) void pack_a(const float* __restrict__ X,
                                              float* __restrict__ Xf)
{
    int i4 = blockIdx.x * 256 + threadIdx.x;
    if (i4 >= NTOK * CC / 4) return;
    int m = i4 / (CC / 4);
    int k = (i4 - m * (CC / 4)) * 4;
    float4 v = ((const float4*)X)[i4];
    int base = afrag_off(m, k);       // k 4-aligned: +4 per k step, same j-bits
    Xf[base + 0]  = tf32r(v.x);
    Xf[base + 4]  = tf32r(v.y);
    Xf[base + 8]  = tf32r(v.z);
    Xf[base + 12] = tf32r(v.w);
}

// ===========================================================================
// Weights -> fragment-packed B operands (tf32-rounded).
// ===========================================================================
__global__ __launch_bounds__(256) void transpose_w(
    const float* __restrict__ wq, const float* __restrict__ wk,
    const float* __restrict__ wv, const float* __restrict__ wp,
    float* __restrict__ qT, float* __restrict__ kT,
    float* __restrict__ vT, float* __restrict__ pT)
{
    int idx = blockIdx.x * 256 + threadIdx.x;
    if (idx >= CC * CC) return;
    int n = idx / CC, k = idx - n * CC;
    int h = n >> 6, d = n & 63;
    int src = (h * CC + k) * DD + d;
    int off = bfrag_off(n, k);
    qT[off] = tf32r(wq[src]);
    kT[off] = tf32r(wk[src]);
    vT[off] = tf32r(wv[src]);
    pT[off] = tf32r(wp[k * CC + n]);
}

// ===========================================================================
// Tensor-core tf32 GEMM v3: cp.async 3-stage pipeline, fragment-packed gmem.
//   C[m][n] = sum_k A[m][k]*Bt[n][k] (+bias). CTA 128x128, 8 warps (2m x 4n).
// ===========================================================================
#define STGF 4096                              // floats per operand stage
#define GEMM_SMEM (6 * STGF * (int)sizeof(float))   // 98304 B

__device__ __forceinline__ void gemm_core(
    const float* __restrict__ Af, const float* __restrict__ Bf,
    const float* __restrict__ bias, float* __restrict__ Cout,
    int m_ct, int n_ct, float* sm)
{
    const int tid = threadIdx.x;
    const int wid = tid >> 5, lane = tid & 31;
    const int gid = lane >> 2, tig = lane & 3;
    const int warp_m = wid & 1;
    const int warp_n = wid >> 1;

    const uint32_t smb = smem_u32(sm);
    const float* Asrc = Af + ((long)m_ct * NCHUNK << 12) + tid * 4;
    const float* Bsrc = Bf + ((long)n_ct * NCHUNK << 12) + tid * 4;
    const uint32_t dA = smb + tid * 16;
    const uint32_t dB = smb + 3 * STGF * 4 + tid * 16;

    // One stage = 4096 floats = 16 KB; 256 threads x 4 cp16 = full stage.
    // prologue: stages 0..2 <- chunks 0..2
#pragma unroll
    for (int s = 0; s < 3; s++) {
#pragma unroll
        for (int i = 0; i < 4; i++) {
            cp16(dA + s * (STGF * 4) + i * 4096, Asrc + s * STGF + i * 1024);
            cp16(dB + s * (STGF * 4) + i * 4096, Bsrc + s * STGF + i * 1024);
        }
        CP_COMMIT();
    }

    float acc[4][4][4];
#pragma unroll
    for (int i = 0; i < 4; i++)
#pragma unroll
        for (int j = 0; j < 4; j++)
#pragma unroll
            for (int r = 0; r < 4; r++) acc[i][j][r] = 0.0f;

    for (int c = 0; c < NCHUNK; c++) {
        const int s = c - (c / 3) * 3;     // c % 3
        CP_WAIT2();
        __syncthreads();

        const float* As = sm + s * STGF;
        const float* Bs = sm + (3 + s) * STGF;

#pragma unroll
        for (int kp = 0; kp < 2; kp++) {
            uint4 bfv[4];
#pragma unroll
            for (int nt = 0; nt < 4; nt++)
                bfv[nt] = *(const uint4*)(Bs +
                    (((warp_n * 4 + nt) * 2 + kp) << 7) + lane * 4);
#pragma unroll
            for (int hf = 0; hf < 2; hf++) {
                const int ks = kp * 2 + hf;
                uint4 afv[4];
#pragma unroll
                for (int mt = 0; mt < 4; mt++)
                    afv[mt] = *(const uint4*)(As +
                        (((warp_m * 4 + mt) * 4 + ks) << 7) + lane * 4);
#pragma unroll
                for (int mt = 0; mt < 4; mt++) {
#pragma unroll
                    for (int nt = 0; nt < 4; nt++) {
                        uint32_t b2[2];
                        if (hf == 0) { b2[0] = bfv[nt].x; b2[1] = bfv[nt].y; }
                        else         { b2[0] = bfv[nt].z; b2[1] = bfv[nt].w; }
                        mma_tf32(acc[mt][nt], (const uint32_t*)&afv[mt], b2);
                    }
                }
            }
        }

        __syncthreads();                   // all warps done reading stage s
        if (c + 3 < NCHUNK) {
#pragma unroll
            for (int i = 0; i < 4; i++) {
                cp16(dA + s * (STGF * 4) + i * 4096,
                     Asrc + (c + 3) * STGF + i * 1024);
                cp16(dB + s * (STGF * 4) + i * 4096,
                     Bsrc + (c + 3) * STGF + i * 1024);
            }
        }
        CP_COMMIT();                       // (possibly empty) group per chunk
    }

    // Epilogue: row-major C with optional bias
#pragma unroll
    for (int mt = 0; mt < 4; mt++) {
#pragma unroll
        for (int nt = 0; nt < 4; nt++) {
            const int n = n_ct * 128 + warp_n * 32 + nt * 8 + 2 * tig;
            float bx = 0.0f, by = 0.0f;
            if (bias) { bx = bias[n]; by = bias[n + 1]; }
            const long mA = m_ct * 128 + warp_m * 64 + mt * 16 + gid;
            float2 v0 = make_float2(acc[mt][nt][0] + bx, acc[mt][nt][1] + by);
            float2 v1 = make_float2(acc[mt][nt][2] + bx, acc[mt][nt][3] + by);
            *(float2*)(Cout + mA * CC + n)       = v0;
            *(float2*)(Cout + (mA + 8) * CC + n) = v1;
        }
    }
}

// Output-projection GEMM (with bias, final fp32 out)
__global__ __launch_bounds__(256, 2) void gemm_mma(
    const float* __restrict__ Af, const float* __restrict__ Bf,
    const float* __restrict__ bias, float* __restrict__ Cout)
{
    extern __shared__ __align__(16) float sm[];
    gemm_core(Af, Bf, bias, Cout, blockIdx.x, blockIdx.y, sm);
}

// Fused QKV GEMM: grid.y in [0,9): matrix = y/3, n_ct = y%3
__global__ __launch_bounds__(256, 2) void gemm_qkv(
    const float* __restrict__ Xf,
    const float* __restrict__ wqT, const float* __restrict__ wkT,
    const float* __restrict__ wvT,
    float* __restrict__ qO, float* __restrict__ kO, float* __restrict__ vO)
{
    extern __shared__ __align__(16) float sm[];
    const int mat  = blockIdx.y / 3;
    const int n_ct = blockIdx.y % 3;
    const float* Bf = (mat == 0) ? wqT : (mat == 1) ? wkT : wvT;
    float* Cout     = (mat == 0) ? qO  : (mat == 1) ? kO  : vO;
    gemm_core(Xf, Bf, nullptr, Cout, blockIdx.x, n_ct, sm);
}

// ===========================================================================
// Tensor-core causal flash attention (round-5 math; epilogue writes
// fragment-packed + tf32-rounded g_attn for the projection GEMM).
//   grid = (T/64, H, B), block = 128 (4 warps, 16 query rows each).
// ===========================================================================
#define ASTR 68
#define ATILE (64 * ASTR)
#define ATTN_SMEM (4 * ATILE * (int)sizeof(float))

__global__ __launch_bounds__(128) void attn_mma(
    const float* __restrict__ Q, const float* __restrict__ K,
    const float* __restrict__ V, float* __restrict__ O)
{
    extern __shared__ __align__(16) float sm[];
    float* Qs = sm;
    float* Ks = sm + ATILE;
    float* Vt = sm + 2 * ATILE;
    float* Ps = sm + 3 * ATILE;

    const int qb  = blockIdx.x;
    const int h   = blockIdx.y;
    const int b   = blockIdx.z;
    const int tid = threadIdx.x;
    const int wid = tid >> 5, lane = tid & 31;
    const int gid = lane >> 2, tig = lane & 3;
    const int mrow = wid * 16 + gid;

    const long qbase = ((long)(b * TT + qb * 64)) * CC + h * DD;

#pragma unroll
    for (int it = 0; it < 8; it++) {
        const int f = it * 128 + tid;
        const int r = f >> 4, d = (f & 15) * 4;
        float4 v = *(const float4*)(Q + qbase + (long)r * CC + d);
        float* qs = Qs + r * ASTR + d;
        qs[0] = tf32r(v.x); qs[1] = tf32r(v.y);
        qs[2] = tf32r(v.z); qs[3] = tf32r(v.w);
    }

    float o[8][4];
#pragma unroll
    for (int nt = 0; nt < 8; nt++)
#pragma unroll
        for (int r = 0; r < 4; r++) o[nt][r] = 0.0f;
    float m0 = -1e30f, m8 = -1e30f, l0 = 0.0f, l8 = 0.0f;

    __syncthreads();

    for (int kb = 0; kb <= qb; kb++) {
        const long kbase = ((long)(b * TT + kb * 64)) * CC + h * DD;

#pragma unroll
        for (int it = 0; it < 8; it++) {
            const int f = it * 128 + tid;
            const int r = f >> 4, d = (f & 15) * 4;
            float4 kv = *(const float4*)(K + kbase + (long)r * CC + d);
            float* ks = Ks + r * ASTR + d;
            ks[0] = tf32r(kv.x); ks[1] = tf32r(kv.y);
            ks[2] = tf32r(kv.z); ks[3] = tf32r(kv.w);
            float4 vv = *(const float4*)(V + kbase + (long)r * CC + d);
            Vt[(d + 0) * ASTR + r] = tf32r(vv.x);
            Vt[(d + 1) * ASTR + r] = tf32r(vv.y);
            Vt[(d + 2) * ASTR + r] = tf32r(vv.z);
            Vt[(d + 3) * ASTR + r] = tf32r(vv.w);
        }
        __syncthreads();

        float s[8][4];
#pragma unroll
        for (int nt = 0; nt < 8; nt++)
#pragma unroll
            for (int r = 0; r < 4; r++) s[nt][r] = 0.0f;

        const uint32_t* Qu = (const uint32_t*)Qs;
        const uint32_t* Ku = (const uint32_t*)Ks;
#pragma unroll
        for (int ks = 0; ks < 8; ks++) {
            uint32_t af[4];
            const int col = ks * 8 + tig;
            af[0] = Qu[mrow * ASTR + col];
            af[1] = Qu[(mrow + 8) * ASTR + col];
            af[2] = Qu[mrow * ASTR + col + 4];
            af[3] = Qu[(mrow + 8) * ASTR + col + 4];
#pragma unroll
            for (int nt = 0; nt < 8; nt++) {
                uint32_t bf[2];
                bf[0] = Ku[(nt * 8 + gid) * ASTR + col];
                bf[1] = Ku[(nt * 8 + gid) * ASTR + col + 4];
                mma_tf32(s[nt], af, bf);
            }
        }

        const bool diag = (kb == qb);
        const float scale = 0.125f;
        float rmax0 = -1e30f, rmax8 = -1e30f;
#pragma unroll
        for (int nt = 0; nt < 8; nt++) {
            const int c0 = nt * 8 + 2 * tig;
#pragma unroll
            for (int r = 0; r < 4; r++) {
                const int col = c0 + (r & 1);
                const int row = mrow + ((r >> 1) << 3);
                float v = s[nt][r] * scale;
                if (diag && col > row) v = -1e30f;
                s[nt][r] = v;
                if (r < 2) rmax0 = fmaxf(rmax0, v);
                else       rmax8 = fmaxf(rmax8, v);
            }
        }
        rmax0 = fmaxf(rmax0, __shfl_xor_sync(0xffffffffu, rmax0, 1));
        rmax0 = fmaxf(rmax0, __shfl_xor_sync(0xffffffffu, rmax0, 2));
        rmax8 = fmaxf(rmax8, __shfl_xor_sync(0xffffffffu, rmax8, 1));
        rmax8 = fmaxf(rmax8, __shfl_xor_sync(0xffffffffu, rmax8, 2));

        const float mn0 = fmaxf(m0, rmax0);
        const float mn8 = fmaxf(m8, rmax8);
        const float corr0 = __expf(m0 - mn0);
        const float corr8 = __expf(m8 - mn8);
        m0 = mn0; m8 = mn8;

        float ls0 = 0.0f, ls8 = 0.0f;
#pragma unroll
        for (int nt = 0; nt < 8; nt++) {
            float p0 = __expf(s[nt][0] - mn0);
            float p1 = __expf(s[nt][1] - mn0);
            float p2 = __expf(s[nt][2] - mn8);
            float p3 = __expf(s[nt][3] - mn8);
            s[nt][0] = p0; s[nt][1] = p1; s[nt][2] = p2; s[nt][3] = p3;
            ls0 += p0 + p1;
            ls8 += p2 + p3;
        }
        ls0 += __shfl_xor_sync(0xffffffffu, ls0, 1);
        ls0 += __shfl_xor_sync(0xffffffffu, ls0, 2);
        ls8 += __shfl_xor_sync(0xffffffffu, ls8, 1);
        ls8 += __shfl_xor_sync(0xffffffffu, ls8, 2);

        l0 = l0 * corr0 + ls0;
        l8 = l8 * corr8 + ls8;
#pragma unroll
        for (int nt = 0; nt < 8; nt++) {
            o[nt][0] *= corr0; o[nt][1] *= corr0;
            o[nt][2] *= corr8; o[nt][3] *= corr8;
        }

#pragma unroll
        for (int nt = 0; nt < 8; nt++) {
            float* p0 = Ps + mrow * ASTR + nt * 8 + 2 * tig;
            p0[0]            = tf32r(s[nt][0]);
            p0[1]            = tf32r(s[nt][1]);
            p0[8 * ASTR + 0] = tf32r(s[nt][2]);
            p0[8 * ASTR + 1] = tf32r(s[nt][3]);
        }
        __syncwarp();

        const uint32_t* Pu = (const uint32_t*)Ps;
        const uint32_t* Vu = (const uint32_t*)Vt;
#pragma unroll
        for (int ks = 0; ks < 8; ks++) {
            uint32_t af[4];
            const int col = ks * 8 + tig;
            af[0] = Pu[mrow * ASTR + col];
            af[1] = Pu[(mrow + 8) * ASTR + col];
            af[2] = Pu[mrow * ASTR + col + 4];
            af[3] = Pu[(mrow + 8) * ASTR + col + 4];
#pragma unroll
            for (int nt = 0; nt < 8; nt++) {
                uint32_t bf[2];
                bf[0] = Vu[(nt * 8 + gid) * ASTR + col];
                bf[1] = Vu[(nt * 8 + gid) * ASTR + col + 4];
                mma_tf32(o[nt], af, bf);
            }
        }
        __syncthreads();
    }

    // Epilogue: write fragment-packed + tf32-rounded A operand for proj GEMM
    const float inv0 = 1.0f / l0;
    const float inv8 = 1.0f / l8;
    const int rowg = b * TT + qb * 64 + mrow;
#pragma unroll
    for (int nt = 0; nt < 8; nt++) {
        const int colg = h * 64 + nt * 8 + 2 * tig;
        O[afrag_off(rowg,     colg)]     = tf32r(o[nt][0] * inv0);
        O[afrag_off(rowg,     colg + 1)] = tf32r(o[nt][1] * inv0);
        O[afrag_off(rowg + 8, colg)]     = tf32r(o[nt][2] * inv8);
        O[afrag_off(rowg + 8, colg + 1)] = tf32r(o[nt][3] * inv8);
    }
}

// ===========================================================================
extern "C" void kernel_launch(void* const* d_in, const int* in_sizes, int n_in,
                              void* d_out, int out_size)
{
    const float* x  = (const float*)d_in[0];
    const float* wq = (const float*)d_in[1];
    const float* wk = (const float*)d_in[2];
    const float* wv = (const float*)d_in[3];
    const float* wp = (const float*)d_in[4];
    const float* bp = (const float*)d_in[5];
    float* out = (float*)d_out;

    float *xf, *qp, *kp, *vp, *ap, *wqT, *wkT, *wvT, *wpT;
    cudaGetSymbolAddress((void**)&xf,  g_xf);
    cudaGetSymbolAddress((void**)&qp,  g_q);
    cudaGetSymbolAddress((void**)&kp,  g_k);
    cudaGetSymbolAddress((void**)&vp,  g_v);
    cudaGetSymbolAddress((void**)&ap,  g_attn);
    cudaGetSymbolAddress((void**)&wqT, g_wqT);
    cudaGetSymbolAddress((void**)&wkT, g_wkT);
    cudaGetSymbolAddress((void**)&wvT, g_wvT);
    cudaGetSymbolAddress((void**)&wpT, g_wpT);

    transpose_w<<<(CC * CC + 255) / 256, 256>>>(wq, wk, wv, wp, wqT, wkT, wvT, wpT);
    pack_a<<<(NTOK * CC / 4 + 255) / 256, 256>>>(x, xf);

    cudaFuncSetAttribute(gemm_qkv,
                         cudaFuncAttributeMaxDynamicSharedMemorySize, GEMM_SMEM);
    cudaFuncSetAttribute(gemm_mma,
                         cudaFuncAttributeMaxDynamicSharedMemorySize, GEMM_SMEM);
    gemm_qkv<<<dim3(NTOK / 128, 9), 256, GEMM_SMEM>>>(xf, wqT, wkT, wvT, qp, kp, vp);

    cudaFuncSetAttribute(attn_mma,
                         cudaFuncAttributeMaxDynamicSharedMemorySize, ATTN_SMEM);
    attn_mma<<<dim3(TT / 64, HH, BB), 128, ATTN_SMEM>>>(qp, kp, vp, ap);

    gemm_mma<<<dim3(NTOK / 128, CC / 128), 256, GEMM_SMEM>>>(ap, wpT, bp, out);
}

// round 9
// speedup vs baseline: 1.3970x; 1.0578x over previous
#include <cuda_runtime.h>
#include <cstdint>

// Problem constants
#define BB 128
#define TT 256
#define CC 384
#define HH 6
#define DD 64
#define NTOK (BB * TT)   // 32768
#define KTILE 32
#define NCHUNK (CC / KTILE)     // 12

// Scratch (static device globals — no dynamic allocation allowed)
__device__ float g_xf[NTOK * CC];      // x, fragment-packed A operand (GEMM)
__device__ float g_q[NTOK * CC];       // A-frag 64x64 tiles per (b,h,qb)
__device__ float g_k[NTOK * CC];       // B-frag 64x64 tiles per (b,h,kb)
__device__ float g_v[NTOK * CC];       // B-frag (n=d,k=key) tiles
__device__ float g_attn[NTOK * CC];    // fragment-packed A operand (GEMM)
__device__ float g_wqT[CC * CC];       // fragment-packed B operands (GEMM)
__device__ float g_wkT[CC * CC];
__device__ float g_wvT[CC * CC];
__device__ float g_wpT[CC * CC];

// ---------------------------------------------------------------------------
__device__ __forceinline__ float tf32r(float x) {
    uint32_t o;
    asm("cvt.rna.tf32.f32 %0, %1;" : "=r"(o) : "f"(x));
    return __uint_as_float(o);
}

__device__ __forceinline__ void mma_tf32(float* c, const uint32_t* a,
                                         const uint32_t* b) {
    asm volatile(
        "mma.sync.aligned.m16n8k8.row.col.f32.tf32.tf32.f32 "
        "{%0,%1,%2,%3}, {%4,%5,%6,%7}, {%8,%9}, {%0,%1,%2,%3};"
        : "+f"(c[0]), "+f"(c[1]), "+f"(c[2]), "+f"(c[3])
        : "r"(a[0]), "r"(a[1]), "r"(a[2]), "r"(a[3]), "r"(b[0]), "r"(b[1]));
}

__device__ __forceinline__ uint32_t smem_u32(const void* p) {
    uint32_t a;
    asm("{ .reg .u64 t; cvta.to.shared.u64 t, %1; cvt.u32.u64 %0, t; }"
        : "=r"(a) : "l"(p));
    return a;
}

__device__ __forceinline__ void cp16(uint32_t dst, const void* src) {
    asm volatile("cp.async.cg.shared.global [%0], [%1], 16;"
                 :: "r"(dst), "l"(src));
}
#define CP_COMMIT() asm volatile("cp.async.commit_group;" ::: "memory")
#define CP_WAIT2()  asm volatile("cp.async.wait_group 2;" ::: "memory")
#define CP_WAIT0()  asm volatile("cp.async.wait_group 0;" ::: "memory")

// ---------------------------------------------------------------------------
// GEMM fragment-packed layouts (per 128x32 block of 4096 floats)
__device__ __forceinline__ int afrag_off(int m, int k) {
    return (((m >> 7) * NCHUNK + (k >> 5)) << 12)
         + (((((m >> 4) & 7) << 2) + ((k >> 3) & 3)) << 7)
         + ((((m & 7) << 2) + (k & 3)) << 2)
         + ((m >> 3) & 1) + (((k >> 2) & 1) << 1);
}
__device__ __forceinline__ int bfrag_off(int n, int k) {
    return (((n >> 7) * NCHUNK + (k >> 5)) << 12)
         + (((((n >> 3) & 15) << 1) + ((k >> 4) & 1)) << 7)
         + ((((n & 7) << 2) + (k & 3)) << 2)
         + (((k >> 3) & 1) << 1) + ((k >> 2) & 1);
}
// Attention fragment layouts (per 64x64 tile of 4096 floats)
__device__ __forceinline__ int afrag64(int m, int k) {
    return ((((m >> 4) << 3) + (k >> 3)) << 7)
         + ((((m & 7) << 2) + (k & 3)) << 2)
         + ((m >> 3) & 1) + (((k >> 2) & 1) << 1);
}
__device__ __forceinline__ int bfrag64(int n, int k) {
    return ((((n >> 3) << 2) + (k >> 4)) << 7)
         + ((((n & 7) << 2) + (k & 3)) << 2)
         + (((k >> 3) & 1) << 1) + ((k >> 2) & 1);
}

// ===========================================================================
// Pack x into fragment-order A operand (tf32-rounded).
// ===========================================================================
__global__ __launch_bounds__(256) void pack_a(const float* __restrict__ X,
                                              float* __restrict__ Xf)
{
    int i4 = blockIdx.x * 256 + threadIdx.x;
    if (i4 >= NTOK * CC / 4) return;
    int m = i4 / (CC / 4);
    int k = (i4 - m * (CC / 4)) * 4;
    float4 v = ((const float4*)X)[i4];
    int base = afrag_off(m, k);
    Xf[base + 0]  = tf32r(v.x);
    Xf[base + 4]  = tf32r(v.y);
    Xf[base + 8]  = tf32r(v.z);
    Xf[base + 12] = tf32r(v.w);
}

// ===========================================================================
// Weights -> fragment-packed B operands (tf32-rounded).
// ===========================================================================
__global__ __launch_bounds__(256) void transpose_w(
    const float* __restrict__ wq, const float* __restrict__ wk,
    const float* __restrict__ wv, const float* __restrict__ wp,
    float* __restrict__ qT, float* __restrict__ kT,
    float* __restrict__ vT, float* __restrict__ pT)
{
    int idx = blockIdx.x * 256 + threadIdx.x;
    if (idx >= CC * CC) return;
    int n = idx / CC, k = idx - n * CC;
    int h = n >> 6, d = n & 63;
    int src = (h * CC + k) * DD + d;
    int off = bfrag_off(n, k);
    qT[off] = tf32r(wq[src]);
    kT[off] = tf32r(wk[src]);
    vT[off] = tf32r(wv[src]);
    pT[off] = tf32r(wp[k * CC + n]);
}

// ===========================================================================
// Tensor-core tf32 GEMM: cp.async 3-stage pipeline, fragment-packed gmem.
//   MODE 0: row-major C + bias (projection)
//   MODE 1: Q -> attention A-frag tiles   (tf32-rounded)
//   MODE 2: K -> attention B-frag tiles   (tf32-rounded)
//   MODE 3: V -> attention B-frag (n=d,k=key) tiles (tf32-rounded)
// ===========================================================================
#define STGF 4096
#define GEMM_SMEM (6 * STGF * (int)sizeof(float))   // 98304 B

template <int MODE>
__device__ __forceinline__ void gemm_core(
    const float* __restrict__ Af, const float* __restrict__ Bf,
    const float* __restrict__ bias, float* __restrict__ Cout,
    int m_ct, int n_ct, float* sm)
{
    const int tid = threadIdx.x;
    const int wid = tid >> 5, lane = tid & 31;
    const int gid = lane >> 2, tig = lane & 3;
    const int warp_m = wid & 1;
    const int warp_n = wid >> 1;

    const uint32_t smb = smem_u32(sm);
    const float* Asrc = Af + ((long)m_ct * NCHUNK << 12) + tid * 4;
    const float* Bsrc = Bf + ((long)n_ct * NCHUNK << 12) + tid * 4;
    const uint32_t dA = smb + tid * 16;
    const uint32_t dB = smb + 3 * STGF * 4 + tid * 16;

#pragma unroll
    for (int s = 0; s < 3; s++) {
#pragma unroll
        for (int i = 0; i < 4; i++) {
            cp16(dA + s * (STGF * 4) + i * 4096, Asrc + s * STGF + i * 1024);
            cp16(dB + s * (STGF * 4) + i * 4096, Bsrc + s * STGF + i * 1024);
        }
        CP_COMMIT();
    }

    float acc[4][4][4];
#pragma unroll
    for (int i = 0; i < 4; i++)
#pragma unroll
        for (int j = 0; j < 4; j++)
#pragma unroll
            for (int r = 0; r < 4; r++) acc[i][j][r] = 0.0f;

    for (int c = 0; c < NCHUNK; c++) {
        const int s = c - (c / 3) * 3;
        CP_WAIT2();
        __syncthreads();

        const float* As = sm + s * STGF;
        const float* Bs = sm + (3 + s) * STGF;

#pragma unroll
        for (int kp = 0; kp < 2; kp++) {
            uint4 bfv[4];
#pragma unroll
            for (int nt = 0; nt < 4; nt++)
                bfv[nt] = *(const uint4*)(Bs +
                    (((warp_n * 4 + nt) * 2 + kp) << 7) + lane * 4);
#pragma unroll
            for (int hf = 0; hf < 2; hf++) {
                const int ks = kp * 2 + hf;
                uint4 afv[4];
#pragma unroll
                for (int mt = 0; mt < 4; mt++)
                    afv[mt] = *(const uint4*)(As +
                        (((warp_m * 4 + mt) * 4 + ks) << 7) + lane * 4);
#pragma unroll
                for (int mt = 0; mt < 4; mt++) {
#pragma unroll
                    for (int nt = 0; nt < 4; nt++) {
                        uint32_t b2[2];
                        if (hf == 0) { b2[0] = bfv[nt].x; b2[1] = bfv[nt].y; }
                        else         { b2[0] = bfv[nt].z; b2[1] = bfv[nt].w; }
                        mma_tf32(acc[mt][nt], (const uint32_t*)&afv[mt], b2);
                    }
                }
            }
        }

        __syncthreads();
        if (c + 3 < NCHUNK) {
#pragma unroll
            for (int i = 0; i < 4; i++) {
                cp16(dA + s * (STGF * 4) + i * 4096,
                     Asrc + (c + 3) * STGF + i * 1024);
                cp16(dB + s * (STGF * 4) + i * 4096,
                     Bsrc + (c + 3) * STGF + i * 1024);
            }
        }
        CP_COMMIT();
    }

#pragma unroll
    for (int mt = 0; mt < 4; mt++) {
#pragma unroll
        for (int nt = 0; nt < 4; nt++) {
            const int n = n_ct * 128 + warp_n * 32 + nt * 8 + 2 * tig;
            const int m = m_ct * 128 + warp_m * 64 + mt * 16 + gid;
            const float c0 = acc[mt][nt][0], c1 = acc[mt][nt][1];
            const float c2 = acc[mt][nt][2], c3 = acc[mt][nt][3];
            if (MODE == 0) {
                float bx = bias ? bias[n] : 0.0f;
                float by = bias ? bias[n + 1] : 0.0f;
                *(float2*)(Cout + (long)m * CC + n) = make_float2(c0 + bx, c1 + by);
                *(float2*)(Cout + (long)(m + 8) * CC + n) = make_float2(c2 + bx, c3 + by);
            } else {
                const int h = n >> 6, d = n & 63;
                const int b = m >> 8, tl = m & 255;
                const int qb = tl >> 6, ml = tl & 63;
                float* dst = Cout + ((long)(((b * HH + h) << 2) + qb) << 12);
                if (MODE == 1) {            // Q: A-frag(m=token, k=d)
                    dst[afrag64(ml,     d)]     = tf32r(c0);
                    dst[afrag64(ml,     d + 1)] = tf32r(c1);
                    dst[afrag64(ml + 8, d)]     = tf32r(c2);
                    dst[afrag64(ml + 8, d + 1)] = tf32r(c3);
                } else if (MODE == 2) {     // K: B-frag(n=token, k=d)
                    dst[bfrag64(ml,     d)]     = tf32r(c0);
                    dst[bfrag64(ml,     d + 1)] = tf32r(c1);
                    dst[bfrag64(ml + 8, d)]     = tf32r(c2);
                    dst[bfrag64(ml + 8, d + 1)] = tf32r(c3);
                } else {                    // V: B-frag(n=d, k=token)
                    dst[bfrag64(d,     ml)]     = tf32r(c0);
                    dst[bfrag64(d + 1, ml)]     = tf32r(c1);
                    dst[bfrag64(d,     ml + 8)] = tf32r(c2);
                    dst[bfrag64(d + 1, ml + 8)] = tf32r(c3);
                }
            }
        }
    }
}

// Output-projection GEMM (with bias, final fp32 out)
__global__ __launch_bounds__(256, 2) void gemm_mma(
    const float* __restrict__ Af, const float* __restrict__ Bf,
    const float* __restrict__ bias, float* __restrict__ Cout)
{
    extern __shared__ __align__(16) float sm[];
    gemm_core<0>(Af, Bf, bias, Cout, blockIdx.x, blockIdx.y, sm);
}

// Fused QKV GEMM: grid.y in [0,9): matrix = y/3, n_ct = y%3
__global__ __launch_bounds__(256, 2) void gemm_qkv(
    const float* __restrict__ Xf,
    const float* __restrict__ wqT, const float* __restrict__ wkT,
    const float* __restrict__ wvT,
    float* __restrict__ qO, float* __restrict__ kO, float* __restrict__ vO)
{
    extern __shared__ __align__(16) float sm[];
    const int mat  = blockIdx.y / 3;
    const int n_ct = blockIdx.y % 3;
    if (mat == 0)      gemm_core<1>(Xf, wqT, nullptr, qO, blockIdx.x, n_ct, sm);
    else if (mat == 1) gemm_core<2>(Xf, wkT, nullptr, kO, blockIdx.x, n_ct, sm);
    else               gemm_core<3>(Xf, wvT, nullptr, vO, blockIdx.x, n_ct, sm);
}

// ===========================================================================
// Tensor-core causal flash attention v2 — fragment-packed Q/K/V in gmem,
// cp.async tile loads, vectorized fragment LDS.
//   grid = (T/64, H, B), block = 128 (4 warps, warp = 16 query rows).
//   SMEM: Qs, Ks, Vs, Ps — 4 x 16 KB fragment tiles.
// ===========================================================================
#define ATILE_F 4096
#define ATTN_SMEM (4 * ATILE_F * (int)sizeof(float))

__global__ __launch_bounds__(128) void attn_mma(
    const float* __restrict__ Qf, const float* __restrict__ Kf,
    const float* __restrict__ Vf, float* __restrict__ O)
{
    extern __shared__ __align__(16) float sm[];
    float* Qs = sm;
    float* Ks = sm + ATILE_F;
    float* Vs = sm + 2 * ATILE_F;
    float* Ps = sm + 3 * ATILE_F;

    const int qb  = blockIdx.x;
    const int h   = blockIdx.y;
    const int b   = blockIdx.z;
    const int tid = threadIdx.x;
    const int wid = tid >> 5, lane = tid & 31;
    const int gid = lane >> 2, tig = lane & 3;
    const int mrow = wid * 16 + gid;

    const int bh = b * HH + h;
    const uint32_t smb = smem_u32(sm);
    const uint32_t dQ = smb + tid * 16;
    const uint32_t dK = smb + ATILE_F * 4 + tid * 16;
    const uint32_t dV = smb + 2 * ATILE_F * 4 + tid * 16;

    // Q tile (A-frag) — load once
    {
        const float* src = Qf + ((long)((bh << 2) + qb) << 12) + tid * 4;
#pragma unroll
        for (int i = 0; i < 8; i++) cp16(dQ + i * 2048, src + i * 512);
        CP_COMMIT();
    }
    // K/V tile for kb = 0
    {
        const float* sk = Kf + ((long)(bh << 2) << 12) + tid * 4;
        const float* sv = Vf + ((long)(bh << 2) << 12) + tid * 4;
#pragma unroll
        for (int i = 0; i < 8; i++) {
            cp16(dK + i * 2048, sk + i * 512);
            cp16(dV + i * 2048, sv + i * 512);
        }
        CP_COMMIT();
    }

    float o[8][4];
#pragma unroll
    for (int nt = 0; nt < 8; nt++)
#pragma unroll
        for (int r = 0; r < 4; r++) o[nt][r] = 0.0f;
    float m0 = -1e30f, m8 = -1e30f, l0 = 0.0f, l8 = 0.0f;

    for (int kb = 0; kb <= qb; kb++) {
        CP_WAIT0();
        __syncthreads();

        // ---- S = Q K^T ----
        uint4 aq[8];
#pragma unroll
        for (int ks = 0; ks < 8; ks++)
            aq[ks] = *(const uint4*)(Qs + (((wid << 3) + ks) << 7) + lane * 4);

        float s[8][4];
#pragma unroll
        for (int nt = 0; nt < 8; nt++)
#pragma unroll
            for (int r = 0; r < 4; r++) s[nt][r] = 0.0f;

#pragma unroll
        for (int kp = 0; kp < 4; kp++) {
#pragma unroll
            for (int nt = 0; nt < 8; nt++) {
                uint4 bv = *(const uint4*)(Ks + (((nt << 2) + kp) << 7) + lane * 4);
                uint32_t b2[2];
                b2[0] = bv.x; b2[1] = bv.y;
                mma_tf32(s[nt], (const uint32_t*)&aq[2 * kp], b2);
                b2[0] = bv.z; b2[1] = bv.w;
                mma_tf32(s[nt], (const uint32_t*)&aq[2 * kp + 1], b2);
            }
        }

        // ---- scale + causal mask + online softmax ----
        const bool diag = (kb == qb);
        const float scale = 0.125f;
        float rmax0 = -1e30f, rmax8 = -1e30f;
#pragma unroll
        for (int nt = 0; nt < 8; nt++) {
            const int c0 = nt * 8 + 2 * tig;
#pragma unroll
            for (int r = 0; r < 4; r++) {
                const int col = c0 + (r & 1);
                const int row = mrow + ((r >> 1) << 3);
                float v = s[nt][r] * scale;
                if (diag && col > row) v = -1e30f;
                s[nt][r] = v;
                if (r < 2) rmax0 = fmaxf(rmax0, v);
                else       rmax8 = fmaxf(rmax8, v);
            }
        }
        rmax0 = fmaxf(rmax0, __shfl_xor_sync(0xffffffffu, rmax0, 1));
        rmax0 = fmaxf(rmax0, __shfl_xor_sync(0xffffffffu, rmax0, 2));
        rmax8 = fmaxf(rmax8, __shfl_xor_sync(0xffffffffu, rmax8, 1));
        rmax8 = fmaxf(rmax8, __shfl_xor_sync(0xffffffffu, rmax8, 2));

        const float mn0 = fmaxf(m0, rmax0);
        const float mn8 = fmaxf(m8, rmax8);
        const float corr0 = __expf(m0 - mn0);
        const float corr8 = __expf(m8 - mn8);
        m0 = mn0; m8 = mn8;

        float ls0 = 0.0f, ls8 = 0.0f;
#pragma unroll
        for (int nt = 0; nt < 8; nt++) {
            float p0 = __expf(s[nt][0] - mn0);
            float p1 = __expf(s[nt][1] - mn0);
            float p2 = __expf(s[nt][2] - mn8);
            float p3 = __expf(s[nt][3] - mn8);
            s[nt][0] = p0; s[nt][1] = p1; s[nt][2] = p2; s[nt][3] = p3;
            ls0 += p0 + p1;
            ls8 += p2 + p3;
        }
        ls0 += __shfl_xor_sync(0xffffffffu, ls0, 1);
        ls0 += __shfl_xor_sync(0xffffffffu, ls0, 2);
        ls8 += __shfl_xor_sync(0xffffffffu, ls8, 1);
        ls8 += __shfl_xor_sync(0xffffffffu, ls8, 2);

        l0 = l0 * corr0 + ls0;
        l8 = l8 * corr8 + ls8;
#pragma unroll
        for (int nt = 0; nt < 8; nt++) {
            o[nt][0] *= corr0; o[nt][1] *= corr0;
            o[nt][2] *= corr8; o[nt][3] *= corr8;
        }

        // ---- P -> SMEM in A-frag order (warp-private region) ----
#pragma unroll
        for (int nt = 0; nt < 8; nt++) {
            const int k = nt * 8 + 2 * tig;
            Ps[afrag64(mrow,     k)]     = tf32r(s[nt][0]);
            Ps[afrag64(mrow,     k + 1)] = tf32r(s[nt][1]);
            Ps[afrag64(mrow + 8, k)]     = tf32r(s[nt][2]);
            Ps[afrag64(mrow + 8, k + 1)] = tf32r(s[nt][3]);
        }
        __syncwarp();

        // ---- O += P V ----
        uint4 ap[8];
#pragma unroll
        for (int ks = 0; ks < 8; ks++)
            ap[ks] = *(const uint4*)(Ps + (((wid << 3) + ks) << 7) + lane * 4);
#pragma unroll
        for (int kp = 0; kp < 4; kp++) {
#pragma unroll
            for (int nt = 0; nt < 8; nt++) {
                uint4 bv = *(const uint4*)(Vs + (((nt << 2) + kp) << 7) + lane * 4);
                uint32_t b2[2];
                b2[0] = bv.x; b2[1] = bv.y;
                mma_tf32(o[nt], (const uint32_t*)&ap[2 * kp], b2);
                b2[0] = bv.z; b2[1] = bv.w;
                mma_tf32(o[nt], (const uint32_t*)&ap[2 * kp + 1], b2);
            }
        }
        __syncthreads();   // everyone done with Ks/Vs

        if (kb < qb) {     // prefetch next K/V
            const float* sk = Kf + ((long)((bh << 2) + kb + 1) << 12) + tid * 4;
            const float* sv = Vf + ((long)((bh << 2) + kb + 1) << 12) + tid * 4;
#pragma unroll
            for (int i = 0; i < 8; i++) {
                cp16(dK + i * 2048, sk + i * 512);
                cp16(dV + i * 2048, sv + i * 512);
            }
            CP_COMMIT();
        }
    }

    // Epilogue: fragment-packed + tf32-rounded A operand for proj GEMM
    const float inv0 = 1.0f / l0;
    const float inv8 = 1.0f / l8;
    const int rowg = b * TT + qb * 64 + mrow;
#pragma unroll
    for (int nt = 0; nt < 8; nt++) {
        const int colg = h * 64 + nt * 8 + 2 * tig;
        O[afrag_off(rowg,     colg)]     = tf32r(o[nt][0] * inv0);
        O[afrag_off(rowg,     colg + 1)] = tf32r(o[nt][1] * inv0);
        O[afrag_off(rowg + 8, colg)]     = tf32r(o[nt][2] * inv8);
        O[afrag_off(rowg + 8, colg + 1)] = tf32r(o[nt][3] * inv8);
    }
}

// ===========================================================================
extern "C" void kernel_launch(void* const* d_in, const int* in_sizes, int n_in,
                              void* d_out, int out_size)
{
    const float* x  = (const float*)d_in[0];
    const float* wq = (const float*)d_in[1];
    const float* wk = (const float*)d_in[2];
    const float* wv = (const float*)d_in[3];
    const float* wp = (const float*)d_in[4];
    const float* bp = (const float*)d_in[5];
    float* out = (float*)d_out;

    float *xf, *qp, *kp, *vp, *ap, *wqT, *wkT, *wvT, *wpT;
    cudaGetSymbolAddress((void**)&xf,  g_xf);
    cudaGetSymbolAddress((void**)&qp,  g_q);
    cudaGetSymbolAddress((void**)&kp,  g_k);
    cudaGetSymbolAddress((void**)&vp,  g_v);
    cudaGetSymbolAddress((void**)&ap,  g_attn);
    cudaGetSymbolAddress((void**)&wqT, g_wqT);
    cudaGetSymbolAddress((void**)&wkT, g_wkT);
    cudaGetSymbolAddress((void**)&wvT, g_wvT);
    cudaGetSymbolAddress((void**)&wpT, g_wpT);

    transpose_w<<<(CC * CC + 255) / 256, 256>>>(wq, wk, wv, wp, wqT, wkT, wvT, wpT);
    pack_a<<<(NTOK * CC / 4 + 255) / 256, 256>>>(x, xf);

    cudaFuncSetAttribute(gemm_qkv,
                         cudaFuncAttributeMaxDynamicSharedMemorySize, GEMM_SMEM);
    cudaFuncSetAttribute(gemm_mma,
                         cudaFuncAttributeMaxDynamicSharedMemorySize, GEMM_SMEM);
    gemm_qkv<<<dim3(NTOK / 128, 9), 256, GEMM_SMEM>>>(xf, wqT, wkT, wvT, qp, kp, vp);

    cudaFuncSetAttribute(attn_mma,
                         cudaFuncAttributeMaxDynamicSharedMemorySize, ATTN_SMEM);
    attn_mma<<<dim3(TT / 64, HH, BB), 128, ATTN_SMEM>>>(qp, kp, vp, ap);

    gemm_mma<<<dim3(NTOK / 128, CC / 128), 256, GEMM_SMEM>>>(ap, wpT, bp, out);
}

// round 10
// speedup vs baseline: 1.4157x; 1.0133x over previous
#include <cuda_runtime.h>
#include <cstdint>

// Problem constants
#define BB 128
#define TT 256
#define CC 384
#define HH 6
#define DD 64
#define NTOK (BB * TT)   // 32768
#define KTILE 32
#define NCHUNK (CC / KTILE)     // 12

// Scratch (static device globals — no dynamic allocation allowed)
__device__ float g_xf[NTOK * CC];      // x, fragment-packed A operand (GEMM)
__device__ float g_q[NTOK * CC];       // A-frag 64x64 tiles per (b,h,qb)
__device__ float g_k[NTOK * CC];       // B-frag 64x64 tiles per (b,h,kb)
__device__ float g_v[NTOK * CC];       // B-frag (n=d,k=key) tiles
__device__ float g_attn[NTOK * CC];    // fragment-packed A operand (GEMM)
__device__ float g_wqT[CC * CC];       // fragment-packed B operands (GEMM)
__device__ float g_wkT[CC * CC];
__device__ float g_wvT[CC * CC];
__device__ float g_wpT[CC * CC];

// ---------------------------------------------------------------------------
__device__ __forceinline__ float tf32r(float x) {
    uint32_t o;
    asm("cvt.rna.tf32.f32 %0, %1;" : "=r"(o) : "f"(x));
    return __uint_as_float(o);
}

__device__ __forceinline__ void mma_tf32(float* c, const uint32_t* a,
                                         const uint32_t* b) {
    asm volatile(
        "mma.sync.aligned.m16n8k8.row.col.f32.tf32.tf32.f32 "
        "{%0,%1,%2,%3}, {%4,%5,%6,%7}, {%8,%9}, {%0,%1,%2,%3};"
        : "+f"(c[0]), "+f"(c[1]), "+f"(c[2]), "+f"(c[3])
        : "r"(a[0]), "r"(a[1]), "r"(a[2]), "r"(a[3]), "r"(b[0]), "r"(b[1]));
}

__device__ __forceinline__ uint32_t smem_u32(const void* p) {
    uint32_t a;
    asm("{ .reg .u64 t; cvta.to.shared.u64 t, %1; cvt.u32.u64 %0, t; }"
        : "=r"(a) : "l"(p));
    return a;
}

__device__ __forceinline__ void cp16(uint32_t dst, const void* src) {
    asm volatile("cp.async.cg.shared.global [%0], [%1], 16;"
                 :: "r"(dst), "l"(src));
}
#define CP_COMMIT() asm volatile("cp.async.commit_group;" ::: "memory")
#define CP_WAIT1()  asm volatile("cp.async.wait_group 1;" ::: "memory")
#define CP_WAIT0()  asm volatile("cp.async.wait_group 0;" ::: "memory")

// ---------------------------------------------------------------------------
// GEMM fragment-packed layouts (per 128x32 block of 4096 floats)
__device__ __forceinline__ int afrag_off(int m, int k) {
    return (((m >> 7) * NCHUNK + (k >> 5)) << 12)
         + (((((m >> 4) & 7) << 2) + ((k >> 3) & 3)) << 7)
         + ((((m & 7) << 2) + (k & 3)) << 2)
         + ((m >> 3) & 1) + (((k >> 2) & 1) << 1);
}
__device__ __forceinline__ int bfrag_off(int n, int k) {
    return (((n >> 7) * NCHUNK + (k >> 5)) << 12)
         + (((((n >> 3) & 15) << 1) + ((k >> 4) & 1)) << 7)
         + ((((n & 7) << 2) + (k & 3)) << 2)
         + (((k >> 3) & 1) << 1) + ((k >> 2) & 1);
}
// Attention fragment layouts (per 64x64 tile of 4096 floats)
__device__ __forceinline__ int afrag64(int m, int k) {
    return ((((m >> 4) << 3) + (k >> 3)) << 7)
         + ((((m & 7) << 2) + (k & 3)) << 2)
         + ((m >> 3) & 1) + (((k >> 2) & 1) << 1);
}
__device__ __forceinline__ int bfrag64(int n, int k) {
    return ((((n >> 3) << 2) + (k >> 4)) << 7)
         + ((((n & 7) << 2) + (k & 3)) << 2)
         + (((k >> 3) & 1) << 1) + ((k >> 2) & 1);
}

// ===========================================================================
// Pack x into fragment-order A operand (tf32-rounded).
// ===========================================================================
__global__ __launch_bounds__(256) void pack_a(const float* __restrict__ X,
                                              float* __restrict__ Xf)
{
    int i4 = blockIdx.x * 256 + threadIdx.x;
    if (i4 >= NTOK * CC / 4) return;
    int m = i4 / (CC / 4);
    int k = (i4 - m * (CC / 4)) * 4;
    float4 v = ((const float4*)X)[i4];
    int base = afrag_off(m, k);
    Xf[base + 0]  = tf32r(v.x);
    Xf[base + 4]  = tf32r(v.y);
    Xf[base + 8]  = tf32r(v.z);
    Xf[base + 12] = tf32r(v.w);
}

// ===========================================================================
// Weights -> fragment-packed B operands (tf32-rounded).
// ===========================================================================
__global__ __launch_bounds__(256) void transpose_w(
    const float* __restrict__ wq, const float* __restrict__ wk,
    const float* __restrict__ wv, const float* __restrict__ wp,
    float* __restrict__ qT, float* __restrict__ kT,
    float* __restrict__ vT, float* __restrict__ pT)
{
    int idx = blockIdx.x * 256 + threadIdx.x;
    if (idx >= CC * CC) return;
    int n = idx / CC, k = idx - n * CC;
    int h = n >> 6, d = n & 63;
    int src = (h * CC + k) * DD + d;
    int off = bfrag_off(n, k);
    qT[off] = tf32r(wq[src]);
    kT[off] = tf32r(wk[src]);
    vT[off] = tf32r(wv[src]);
    pT[off] = tf32r(wp[k * CC + n]);
}

// ===========================================================================
// Tensor-core tf32 GEMM: cp.async 3-stage, ONE __syncthreads per chunk.
//   MODE 0: row-major C + bias; MODE 1/2/3: Q/K/V attention-fragment tiles.
// ===========================================================================
#define STGF 4096
#define GEMM_SMEM (6 * STGF * (int)sizeof(float))   // 98304 B

template <int MODE>
__device__ __forceinline__ void gemm_core(
    const float* __restrict__ Af, const float* __restrict__ Bf,
    const float* __restrict__ bias, float* __restrict__ Cout,
    int m_ct, int n_ct, float* sm)
{
    const int tid = threadIdx.x;
    const int wid = tid >> 5, lane = tid & 31;
    const int gid = lane >> 2, tig = lane & 3;
    const int warp_m = wid & 1;
    const int warp_n = wid >> 1;

    const uint32_t smb = smem_u32(sm);
    const float* Asrc = Af + ((long)m_ct * NCHUNK << 12) + tid * 4;
    const float* Bsrc = Bf + ((long)n_ct * NCHUNK << 12) + tid * 4;
    const uint32_t dA = smb + tid * 16;
    const uint32_t dB = smb + 3 * STGF * 4 + tid * 16;

    // prologue: chunks 0,1 -> stages 0,1 (one commit group each)
#pragma unroll
    for (int s = 0; s < 2; s++) {
#pragma unroll
        for (int i = 0; i < 4; i++) {
            cp16(dA + s * (STGF * 4) + i * 4096, Asrc + s * STGF + i * 1024);
            cp16(dB + s * (STGF * 4) + i * 4096, Bsrc + s * STGF + i * 1024);
        }
        CP_COMMIT();
    }

    float acc[4][4][4];
#pragma unroll
    for (int i = 0; i < 4; i++)
#pragma unroll
        for (int j = 0; j < 4; j++)
#pragma unroll
            for (int r = 0; r < 4; r++) acc[i][j][r] = 0.0f;

    for (int c = 0; c < NCHUNK; c++) {
        const int s = c - (c / 3) * 3;     // c % 3
        CP_WAIT1();                        // chunk c landed (c+1 may fly)
        __syncthreads();                   // also fences readers of stage (c+2)%3

        if (c + 2 < NCHUNK) {              // prefetch chunk c+2 -> stage (c+2)%3
            const int sp = (c + 2) - ((c + 2) / 3) * 3;
#pragma unroll
            for (int i = 0; i < 4; i++) {
                cp16(dA + sp * (STGF * 4) + i * 4096,
                     Asrc + (c + 2) * STGF + i * 1024);
                cp16(dB + sp * (STGF * 4) + i * 4096,
                     Bsrc + (c + 2) * STGF + i * 1024);
            }
        }
        CP_COMMIT();

        const float* As = sm + s * STGF;
        const float* Bs = sm + (3 + s) * STGF;

#pragma unroll
        for (int kp = 0; kp < 2; kp++) {
            uint4 bfv[4];
#pragma unroll
            for (int nt = 0; nt < 4; nt++)
                bfv[nt] = *(const uint4*)(Bs +
                    (((warp_n * 4 + nt) * 2 + kp) << 7) + lane * 4);
#pragma unroll
            for (int hf = 0; hf < 2; hf++) {
                const int ks = kp * 2 + hf;
                uint4 afv[4];
#pragma unroll
                for (int mt = 0; mt < 4; mt++)
                    afv[mt] = *(const uint4*)(As +
                        (((warp_m * 4 + mt) * 4 + ks) << 7) + lane * 4);
#pragma unroll
                for (int mt = 0; mt < 4; mt++) {
#pragma unroll
                    for (int nt = 0; nt < 4; nt++) {
                        uint32_t b2[2];
                        if (hf == 0) { b2[0] = bfv[nt].x; b2[1] = bfv[nt].y; }
                        else         { b2[0] = bfv[nt].z; b2[1] = bfv[nt].w; }
                        mma_tf32(acc[mt][nt], (const uint32_t*)&afv[mt], b2);
                    }
                }
            }
        }
    }

#pragma unroll
    for (int mt = 0; mt < 4; mt++) {
#pragma unroll
        for (int nt = 0; nt < 4; nt++) {
            const int n = n_ct * 128 + warp_n * 32 + nt * 8 + 2 * tig;
            const int m = m_ct * 128 + warp_m * 64 + mt * 16 + gid;
            const float c0 = acc[mt][nt][0], c1 = acc[mt][nt][1];
            const float c2 = acc[mt][nt][2], c3 = acc[mt][nt][3];
            if (MODE == 0) {
                float bx = bias ? bias[n] : 0.0f;
                float by = bias ? bias[n + 1] : 0.0f;
                *(float2*)(Cout + (long)m * CC + n) = make_float2(c0 + bx, c1 + by);
                *(float2*)(Cout + (long)(m + 8) * CC + n) = make_float2(c2 + bx, c3 + by);
            } else {
                const int h = n >> 6, d = n & 63;
                const int b = m >> 8, tl = m & 255;
                const int qb = tl >> 6, ml = tl & 63;
                float* dst = Cout + ((long)(((b * HH + h) << 2) + qb) << 12);
                if (MODE == 1) {            // Q: A-frag(m=token, k=d)
                    dst[afrag64(ml,     d)]     = tf32r(c0);
                    dst[afrag64(ml,     d + 1)] = tf32r(c1);
                    dst[afrag64(ml + 8, d)]     = tf32r(c2);
                    dst[afrag64(ml + 8, d + 1)] = tf32r(c3);
                } else if (MODE == 2) {     // K: B-frag(n=token, k=d)
                    dst[bfrag64(ml,     d)]     = tf32r(c0);
                    dst[bfrag64(ml,     d + 1)] = tf32r(c1);
                    dst[bfrag64(ml + 8, d)]     = tf32r(c2);
                    dst[bfrag64(ml + 8, d + 1)] = tf32r(c3);
                } else {                    // V: B-frag(n=d, k=token)
                    dst[bfrag64(d,     ml)]     = tf32r(c0);
                    dst[bfrag64(d + 1, ml)]     = tf32r(c1);
                    dst[bfrag64(d,     ml + 8)] = tf32r(c2);
                    dst[bfrag64(d + 1, ml + 8)] = tf32r(c3);
                }
            }
        }
    }
}

// Output-projection GEMM (with bias, final fp32 out)
__global__ __launch_bounds__(256, 2) void gemm_mma(
    const float* __restrict__ Af, const float* __restrict__ Bf,
    const float* __restrict__ bias, float* __restrict__ Cout)
{
    extern __shared__ __align__(16) float sm[];
    gemm_core<0>(Af, Bf, bias, Cout, blockIdx.x, blockIdx.y, sm);
}

// Fused QKV GEMM: grid.y in [0,9): matrix = y/3, n_ct = y%3
__global__ __launch_bounds__(256, 2) void gemm_qkv(
    const float* __restrict__ Xf,
    const float* __restrict__ wqT, const float* __restrict__ wkT,
    const float* __restrict__ wvT,
    float* __restrict__ qO, float* __restrict__ kO, float* __restrict__ vO)
{
    extern __shared__ __align__(16) float sm[];
    const int mat  = blockIdx.y / 3;
    const int n_ct = blockIdx.y % 3;
    if (mat == 0)      gemm_core<1>(Xf, wqT, nullptr, qO, blockIdx.x, n_ct, sm);
    else if (mat == 1) gemm_core<2>(Xf, wkT, nullptr, kO, blockIdx.x, n_ct, sm);
    else               gemm_core<3>(Xf, wvT, nullptr, vO, blockIdx.x, n_ct, sm);
}

// ===========================================================================
// Tensor-core causal flash attention v3 — 128-row query tile, 8 warps.
//   grid = (T/128, H, B), block = 256. Warp w handles query rows
//   [qbt*128 + w*16, +16). Fully-masked warps skip compute (keep barriers).
//   SMEM: Q 2 tiles | K 1 | V 1 | P 2 tiles = 96 KB.
// ===========================================================================
#define ATILE_F 4096
#define ATTN_SMEM (6 * ATILE_F * (int)sizeof(float))

__global__ __launch_bounds__(256, 2) void attn_mma(
    const float* __restrict__ Qf, const float* __restrict__ Kf,
    const float* __restrict__ Vf, float* __restrict__ O)
{
    extern __shared__ __align__(16) float sm[];
    float* Qs = sm;                       // 2 tiles
    float* Ks = sm + 2 * ATILE_F;
    float* Vs = sm + 3 * ATILE_F;
    float* Ps = sm + 4 * ATILE_F;         // 2 tiles

    const int qbt = blockIdx.x;           // 128-row query tile
    const int h   = blockIdx.y;
    const int b   = blockIdx.z;
    const int tid = threadIdx.x;
    const int wid = tid >> 5, lane = tid & 31;
    const int gid = lane >> 2, tig = lane & 3;
    const int qtile = wid >> 2;           // which 64-tile inside query tile
    const int lsub  = wid & 3;            // 16-row group within 64-tile
    const int mrow  = lsub * 16 + gid;    // row within 64-tile
    const int growb = qbt * 128 + wid * 16;   // warp's first global row

    const int bh = b * HH + h;
    const uint32_t smb = smem_u32(sm);
    const uint32_t dQ = smb + tid * 16;
    const uint32_t dK = smb + 2 * ATILE_F * 4 + tid * 16;
    const uint32_t dV = smb + 3 * ATILE_F * 4 + tid * 16;

    // Q: two consecutive 64-tiles (32 KB)
    {
        const float* src = Qf + ((long)((bh << 2) + (qbt << 1)) << 12) + tid * 4;
#pragma unroll
        for (int i = 0; i < 8; i++) cp16(dQ + i * 4096, src + i * 1024);
        CP_COMMIT();
    }
    // K/V tile kb = 0
    {
        const float* sk = Kf + ((long)(bh << 2) << 12) + tid * 4;
        const float* sv = Vf + ((long)(bh << 2) << 12) + tid * 4;
#pragma unroll
        for (int i = 0; i < 4; i++) {
            cp16(dK + i * 4096, sk + i * 1024);
            cp16(dV + i * 4096, sv + i * 1024);
        }
        CP_COMMIT();
    }

    float o[8][4];
#pragma unroll
    for (int nt = 0; nt < 8; nt++)
#pragma unroll
        for (int r = 0; r < 4; r++) o[nt][r] = 0.0f;
    float m0 = -1e30f, m8 = -1e30f, l0 = 0.0f, l8 = 0.0f;

    const int nkb = 2 * qbt + 2;          // kb blocks covering causal span

    for (int kb = 0; kb < nkb; kb++) {
        CP_WAIT0();
        __syncthreads();

        const bool active = (kb * 64) <= (growb + 15);
        if (active) {
            // ---- S = Q K^T ----
            uint4 aq[8];
#pragma unroll
            for (int ks = 0; ks < 8; ks++)
                aq[ks] = *(const uint4*)(Qs + qtile * ATILE_F +
                    (((lsub << 3) + ks) << 7) + lane * 4);

            float s[8][4];
#pragma unroll
            for (int nt = 0; nt < 8; nt++)
#pragma unroll
                for (int r = 0; r < 4; r++) s[nt][r] = 0.0f;

#pragma unroll
            for (int kp = 0; kp < 4; kp++) {
#pragma unroll
                for (int nt = 0; nt < 8; nt++) {
                    uint4 bv = *(const uint4*)(Ks + (((nt << 2) + kp) << 7) + lane * 4);
                    uint32_t b2[2];
                    b2[0] = bv.x; b2[1] = bv.y;
                    mma_tf32(s[nt], (const uint32_t*)&aq[2 * kp], b2);
                    b2[0] = bv.z; b2[1] = bv.w;
                    mma_tf32(s[nt], (const uint32_t*)&aq[2 * kp + 1], b2);
                }
            }

            // ---- scale + causal mask + online softmax ----
            const bool needMask = (kb * 64 + 63) > growb;
            const float scale = 0.125f;
            const int grow0 = growb + gid;
            float rmax0 = -1e30f, rmax8 = -1e30f;
#pragma unroll
            for (int nt = 0; nt < 8; nt++) {
                const int c0 = kb * 64 + nt * 8 + 2 * tig;
#pragma unroll
                for (int r = 0; r < 4; r++) {
                    const int col = c0 + (r & 1);
                    const int row = grow0 + ((r >> 1) << 3);
                    float v = s[nt][r] * scale;
                    if (needMask && col > row) v = -1e30f;
                    s[nt][r] = v;
                    if (r < 2) rmax0 = fmaxf(rmax0, v);
                    else       rmax8 = fmaxf(rmax8, v);
                }
            }
            rmax0 = fmaxf(rmax0, __shfl_xor_sync(0xffffffffu, rmax0, 1));
            rmax0 = fmaxf(rmax0, __shfl_xor_sync(0xffffffffu, rmax0, 2));
            rmax8 = fmaxf(rmax8, __shfl_xor_sync(0xffffffffu, rmax8, 1));
            rmax8 = fmaxf(rmax8, __shfl_xor_sync(0xffffffffu, rmax8, 2));

            const float mn0 = fmaxf(m0, rmax0);
            const float mn8 = fmaxf(m8, rmax8);
            const float corr0 = __expf(m0 - mn0);
            const float corr8 = __expf(m8 - mn8);
            m0 = mn0; m8 = mn8;

            float ls0 = 0.0f, ls8 = 0.0f;
#pragma unroll
            for (int nt = 0; nt < 8; nt++) {
                float p0 = __expf(s[nt][0] - mn0);
                float p1 = __expf(s[nt][1] - mn0);
                float p2 = __expf(s[nt][2] - mn8);
                float p3 = __expf(s[nt][3] - mn8);
                s[nt][0] = p0; s[nt][1] = p1; s[nt][2] = p2; s[nt][3] = p3;
                ls0 += p0 + p1;
                ls8 += p2 + p3;
            }
            ls0 += __shfl_xor_sync(0xffffffffu, ls0, 1);
            ls0 += __shfl_xor_sync(0xffffffffu, ls0, 2);
            ls8 += __shfl_xor_sync(0xffffffffu, ls8, 1);
            ls8 += __shfl_xor_sync(0xffffffffu, ls8, 2);

            l0 = l0 * corr0 + ls0;
            l8 = l8 * corr8 + ls8;
#pragma unroll
            for (int nt = 0; nt < 8; nt++) {
                o[nt][0] *= corr0; o[nt][1] *= corr0;
                o[nt][2] *= corr8; o[nt][3] *= corr8;
            }

            // ---- P -> SMEM (A-frag, warp-private rows) ----
            float* Pw = Ps + qtile * ATILE_F;
#pragma unroll
            for (int nt = 0; nt < 8; nt++) {
                const int k = nt * 8 + 2 * tig;
                Pw[afrag64(mrow,     k)]     = tf32r(s[nt][0]);
                Pw[afrag64(mrow,     k + 1)] = tf32r(s[nt][1]);
                Pw[afrag64(mrow + 8, k)]     = tf32r(s[nt][2]);
                Pw[afrag64(mrow + 8, k + 1)] = tf32r(s[nt][3]);
            }
            __syncwarp();

            // ---- O += P V ----
            uint4 ap[8];
#pragma unroll
            for (int ks = 0; ks < 8; ks++)
                ap[ks] = *(const uint4*)(Pw + (((lsub << 3) + ks) << 7) + lane * 4);
#pragma unroll
            for (int kp = 0; kp < 4; kp++) {
#pragma unroll
                for (int nt = 0; nt < 8; nt++) {
                    uint4 bv = *(const uint4*)(Vs + (((nt << 2) + kp) << 7) + lane * 4);
                    uint32_t b2[2];
                    b2[0] = bv.x; b2[1] = bv.y;
                    mma_tf32(o[nt], (const uint32_t*)&ap[2 * kp], b2);
                    b2[0] = bv.z; b2[1] = bv.w;
                    mma_tf32(o[nt], (const uint32_t*)&ap[2 * kp + 1], b2);
                }
            }
        }
        __syncthreads();                   // all warps done with Ks/Vs

        if (kb + 1 < nkb) {                // prefetch next K/V
            const float* sk = Kf + ((long)((bh << 2) + kb + 1) << 12) + tid * 4;
            const float* sv = Vf + ((long)((bh << 2) + kb + 1) << 12) + tid * 4;
#pragma unroll
            for (int i = 0; i < 4; i++) {
                cp16(dK + i * 4096, sk + i * 1024);
                cp16(dV + i * 4096, sv + i * 1024);
            }
            CP_COMMIT();
        }
    }

    // Epilogue: fragment-packed + tf32-rounded A operand for proj GEMM
    const float inv0 = 1.0f / l0;
    const float inv8 = 1.0f / l8;
    const int rowg = b * TT + qbt * 128 + wid * 16 + gid;
#pragma unroll
    for (int nt = 0; nt < 8; nt++) {
        const int colg = h * 64 + nt * 8 + 2 * tig;
        O[afrag_off(rowg,     colg)]     = tf32r(o[nt][0] * inv0);
        O[afrag_off(rowg,     colg + 1)] = tf32r(o[nt][1] * inv0);
        O[afrag_off(rowg + 8, colg)]     = tf32r(o[nt][2] * inv8);
        O[afrag_off(rowg + 8, colg + 1)] = tf32r(o[nt][3] * inv8);
    }
}

// ===========================================================================
extern "C" void kernel_launch(void* const* d_in, const int* in_sizes, int n_in,
                              void* d_out, int out_size)
{
    const float* x  = (const float*)d_in[0];
    const float* wq = (const float*)d_in[1];
    const float* wk = (const float*)d_in[2];
    const float* wv = (const float*)d_in[3];
    const float* wp = (const float*)d_in[4];
    const float* bp = (const float*)d_in[5];
    float* out = (float*)d_out;

    float *xf, *qp, *kp, *vp, *ap, *wqT, *wkT, *wvT, *wpT;
    cudaGetSymbolAddress((void**)&xf,  g_xf);
    cudaGetSymbolAddress((void**)&qp,  g_q);
    cudaGetSymbolAddress((void**)&kp,  g_k);
    cudaGetSymbolAddress((void**)&vp,  g_v);
    cudaGetSymbolAddress((void**)&ap,  g_attn);
    cudaGetSymbolAddress((void**)&wqT, g_wqT);
    cudaGetSymbolAddress((void**)&wkT, g_wkT);
    cudaGetSymbolAddress((void**)&wvT, g_wvT);
    cudaGetSymbolAddress((void**)&wpT, g_wpT);

    transpose_w<<<(CC * CC + 255) / 256, 256>>>(wq, wk, wv, wp, wqT, wkT, wvT, wpT);
    pack_a<<<(NTOK * CC / 4 + 255) / 256, 256>>>(x, xf);

    cudaFuncSetAttribute(gemm_qkv,
                         cudaFuncAttributeMaxDynamicSharedMemorySize, GEMM_SMEM);
    cudaFuncSetAttribute(gemm_mma,
                         cudaFuncAttributeMaxDynamicSharedMemorySize, GEMM_SMEM);
    gemm_qkv<<<dim3(NTOK / 128, 9), 256, GEMM_SMEM>>>(xf, wqT, wkT, wvT, qp, kp, vp);

    cudaFuncSetAttribute(attn_mma,
                         cudaFuncAttributeMaxDynamicSharedMemorySize, ATTN_SMEM);
    attn_mma<<<dim3(TT / 128, HH, BB), 256, ATTN_SMEM>>>(qp, kp, vp, ap);

    gemm_mma<<<dim3(NTOK / 128, CC / 128), 256, GEMM_SMEM>>>(ap, wpT, bp, out);
}

// round 11
// speedup vs baseline: 1.4472x; 1.0222x over previous
#include <cuda_runtime.h>
#include <cstdint>

// Problem constants
#define BB 128
#define TT 256
#define CC 384
#define HH 6
#define DD 64
#define NTOK (BB * TT)   // 32768
#define KTILE 32
#define NCHUNK (CC / KTILE)     // 12

// Scratch (static device globals — no dynamic allocation allowed)
__device__ float g_xf[NTOK * CC];      // x, fragment-packed A operand (GEMM)
__device__ float g_q[NTOK * CC];       // A-frag 64x64 tiles per (b,h,qb)
__device__ float g_k[NTOK * CC];       // B-frag 64x64 tiles per (b,h,kb)
__device__ float g_v[NTOK * CC];       // B-frag (n=d,k=key) tiles
__device__ float g_attn[NTOK * CC];    // fragment-packed A operand (GEMM)
__device__ float g_wqT[CC * CC];       // fragment-packed B operands (GEMM)
__device__ float g_wkT[CC * CC];
__device__ float g_wvT[CC * CC];
__device__ float g_wpT[CC * CC];

// ---------------------------------------------------------------------------
__device__ __forceinline__ float tf32r(float x) {
    uint32_t o;
    asm("cvt.rna.tf32.f32 %0, %1;" : "=r"(o) : "f"(x));
    return __uint_as_float(o);
}

__device__ __forceinline__ void mma_tf32(float* c, const uint32_t* a,
                                         const uint32_t* b) {
    asm volatile(
        "mma.sync.aligned.m16n8k8.row.col.f32.tf32.tf32.f32 "
        "{%0,%1,%2,%3}, {%4,%5,%6,%7}, {%8,%9}, {%0,%1,%2,%3};"
        : "+f"(c[0]), "+f"(c[1]), "+f"(c[2]), "+f"(c[3])
        : "r"(a[0]), "r"(a[1]), "r"(a[2]), "r"(a[3]), "r"(b[0]), "r"(b[1]));
}

__device__ __forceinline__ uint32_t smem_u32(const void* p) {
    uint32_t a;
    asm("{ .reg .u64 t; cvta.to.shared.u64 t, %1; cvt.u32.u64 %0, t; }"
        : "=r"(a) : "l"(p));
    return a;
}

__device__ __forceinline__ void cp16(uint32_t dst, const void* src) {
    asm volatile("cp.async.cg.shared.global [%0], [%1], 16;"
                 :: "r"(dst), "l"(src));
}
#define CP_COMMIT() asm volatile("cp.async.commit_group;" ::: "memory")
#define CP_WAIT1()  asm volatile("cp.async.wait_group 1;" ::: "memory")
#define CP_WAIT0()  asm volatile("cp.async.wait_group 0;" ::: "memory")

// ---------------------------------------------------------------------------
// GEMM fragment-packed layouts (per 128x32 block of 4096 floats)
__device__ __forceinline__ int afrag_off(int m, int k) {
    return (((m >> 7) * NCHUNK + (k >> 5)) << 12)
         + (((((m >> 4) & 7) << 2) + ((k >> 3) & 3)) << 7)
         + ((((m & 7) << 2) + (k & 3)) << 2)
         + ((m >> 3) & 1) + (((k >> 2) & 1) << 1);
}
__device__ __forceinline__ int bfrag_off(int n, int k) {
    return (((n >> 7) * NCHUNK + (k >> 5)) << 12)
         + (((((n >> 3) & 15) << 1) + ((k >> 4) & 1)) << 7)
         + ((((n & 7) << 2) + (k & 3)) << 2)
         + (((k >> 3) & 1) << 1) + ((k >> 2) & 1);
}
// Attention fragment layouts (per 64x64 tile of 4096 floats)
__device__ __forceinline__ int afrag64(int m, int k) {
    return ((((m >> 4) << 3) + (k >> 3)) << 7)
         + ((((m & 7) << 2) + (k & 3)) << 2)
         + ((m >> 3) & 1) + (((k >> 2) & 1) << 1);
}
__device__ __forceinline__ int bfrag64(int n, int k) {
    return ((((n >> 3) << 2) + (k >> 4)) << 7)
         + ((((n & 7) << 2) + (k & 3)) << 2)
         + (((k >> 3) & 1) << 1) + ((k >> 2) & 1);
}

// ===========================================================================
// Pack x into fragment-order A operand (tf32-rounded).
// ===========================================================================
__global__ __launch_bounds__(256) void pack_a(const float* __restrict__ X,
                                              float* __restrict__ Xf)
{
    int i4 = blockIdx.x * 256 + threadIdx.x;
    if (i4 >= NTOK * CC / 4) return;
    int m = i4 / (CC / 4);
    int k = (i4 - m * (CC / 4)) * 4;
    float4 v = ((const float4*)X)[i4];
    int base = afrag_off(m, k);
    Xf[base + 0]  = tf32r(v.x);
    Xf[base + 4]  = tf32r(v.y);
    Xf[base + 8]  = tf32r(v.z);
    Xf[base + 12] = tf32r(v.w);
}

// ===========================================================================
// Weights -> fragment-packed B operands (tf32-rounded).
// ===========================================================================
__global__ __launch_bounds__(256) void transpose_w(
    const float* __restrict__ wq, const float* __restrict__ wk,
    const float* __restrict__ wv, const float* __restrict__ wp,
    float* __restrict__ qT, float* __restrict__ kT,
    float* __restrict__ vT, float* __restrict__ pT)
{
    int idx = blockIdx.x * 256 + threadIdx.x;
    if (idx >= CC * CC) return;
    int n = idx / CC, k = idx - n * CC;
    int h = n >> 6, d = n & 63;
    int src = (h * CC + k) * DD + d;
    int off = bfrag_off(n, k);
    qT[off] = tf32r(wq[src]);
    kT[off] = tf32r(wk[src]);
    vT[off] = tf32r(wv[src]);
    pT[off] = tf32r(wp[k * CC + n]);
}

// ===========================================================================
// Tensor-core tf32 GEMM: cp.async 3-stage, ONE __syncthreads per chunk.
//   MODE 0: row-major C + bias; MODE 1/2/3: Q/K/V attention-fragment tiles.
// ===========================================================================
#define STGF 4096
#define GEMM_SMEM (6 * STGF * (int)sizeof(float))   // 98304 B

template <int MODE>
__device__ __forceinline__ void gemm_core(
    const float* __restrict__ Af, const float* __restrict__ Bf,
    const float* __restrict__ bias, float* __restrict__ Cout,
    int m_ct, int n_ct, float* sm)
{
    const int tid = threadIdx.x;
    const int wid = tid >> 5, lane = tid & 31;
    const int gid = lane >> 2, tig = lane & 3;
    const int warp_m = wid & 1;
    const int warp_n = wid >> 1;

    const uint32_t smb = smem_u32(sm);
    const float* Asrc = Af + ((long)m_ct * NCHUNK << 12) + tid * 4;
    const float* Bsrc = Bf + ((long)n_ct * NCHUNK << 12) + tid * 4;
    const uint32_t dA = smb + tid * 16;
    const uint32_t dB = smb + 3 * STGF * 4 + tid * 16;

    // prologue: chunks 0,1 -> stages 0,1 (one commit group each)
#pragma unroll
    for (int s = 0; s < 2; s++) {
#pragma unroll
        for (int i = 0; i < 4; i++) {
            cp16(dA + s * (STGF * 4) + i * 4096, Asrc + s * STGF + i * 1024);
            cp16(dB + s * (STGF * 4) + i * 4096, Bsrc + s * STGF + i * 1024);
        }
        CP_COMMIT();
    }

    float acc[4][4][4];
#pragma unroll
    for (int i = 0; i < 4; i++)
#pragma unroll
        for (int j = 0; j < 4; j++)
#pragma unroll
            for (int r = 0; r < 4; r++) acc[i][j][r] = 0.0f;

    for (int c = 0; c < NCHUNK; c++) {
        const int s = c - (c / 3) * 3;     // c % 3
        CP_WAIT1();                        // chunk c landed (c+1 may fly)
        __syncthreads();                   // also fences readers of stage (c+2)%3

        if (c + 2 < NCHUNK) {              // prefetch chunk c+2 -> stage (c+2)%3
            const int sp = (c + 2) - ((c + 2) / 3) * 3;
#pragma unroll
            for (int i = 0; i < 4; i++) {
                cp16(dA + sp * (STGF * 4) + i * 4096,
                     Asrc + (c + 2) * STGF + i * 1024);
                cp16(dB + sp * (STGF * 4) + i * 4096,
                     Bsrc + (c + 2) * STGF + i * 1024);
            }
        }
        CP_COMMIT();

        const float* As = sm + s * STGF;
        const float* Bs = sm + (3 + s) * STGF;

#pragma unroll
        for (int kp = 0; kp < 2; kp++) {
            uint4 bfv[4];
#pragma unroll
            for (int nt = 0; nt < 4; nt++)
                bfv[nt] = *(const uint4*)(Bs +
                    (((warp_n * 4 + nt) * 2 + kp) << 7) + lane * 4);
#pragma unroll
            for (int hf = 0; hf < 2; hf++) {
                const int ks = kp * 2 + hf;
                uint4 afv[4];
#pragma unroll
                for (int mt = 0; mt < 4; mt++)
                    afv[mt] = *(const uint4*)(As +
                        (((warp_m * 4 + mt) * 4 + ks) << 7) + lane * 4);
#pragma unroll
                for (int mt = 0; mt < 4; mt++) {
#pragma unroll
                    for (int nt = 0; nt < 4; nt++) {
                        uint32_t b2[2];
                        if (hf == 0) { b2[0] = bfv[nt].x; b2[1] = bfv[nt].y; }
                        else         { b2[0] = bfv[nt].z; b2[1] = bfv[nt].w; }
                        mma_tf32(acc[mt][nt], (const uint32_t*)&afv[mt], b2);
                    }
                }
            }
        }
    }

#pragma unroll
    for (int mt = 0; mt < 4; mt++) {
#pragma unroll
        for (int nt = 0; nt < 4; nt++) {
            const int n = n_ct * 128 + warp_n * 32 + nt * 8 + 2 * tig;
            const int m = m_ct * 128 + warp_m * 64 + mt * 16 + gid;
            const float c0 = acc[mt][nt][0], c1 = acc[mt][nt][1];
            const float c2 = acc[mt][nt][2], c3 = acc[mt][nt][3];
            if (MODE == 0) {
                float bx = bias ? bias[n] : 0.0f;
                float by = bias ? bias[n + 1] : 0.0f;
                *(float2*)(Cout + (long)m * CC + n) = make_float2(c0 + bx, c1 + by);
                *(float2*)(Cout + (long)(m + 8) * CC + n) = make_float2(c2 + bx, c3 + by);
            } else {
                const int h = n >> 6, d = n & 63;
                const int b = m >> 8, tl = m & 255;
                const int qb = tl >> 6, ml = tl & 63;
                float* dst = Cout + ((long)(((b * HH + h) << 2) + qb) << 12);
                if (MODE == 1) {            // Q: A-frag(m=token, k=d)
                    dst[afrag64(ml,     d)]     = tf32r(c0);
                    dst[afrag64(ml,     d + 1)] = tf32r(c1);
                    dst[afrag64(ml + 8, d)]     = tf32r(c2);
                    dst[afrag64(ml + 8, d + 1)] = tf32r(c3);
                } else if (MODE == 2) {     // K: B-frag(n=token, k=d)
                    dst[bfrag64(ml,     d)]     = tf32r(c0);
                    dst[bfrag64(ml,     d + 1)] = tf32r(c1);
                    dst[bfrag64(ml + 8, d)]     = tf32r(c2);
                    dst[bfrag64(ml + 8, d + 1)] = tf32r(c3);
                } else {                    // V: B-frag(n=d, k=token)
                    dst[bfrag64(d,     ml)]     = tf32r(c0);
                    dst[bfrag64(d + 1, ml)]     = tf32r(c1);
                    dst[bfrag64(d,     ml + 8)] = tf32r(c2);
                    dst[bfrag64(d + 1, ml + 8)] = tf32r(c3);
                }
            }
        }
    }
}

// Output-projection GEMM (with bias, final fp32 out)
__global__ __launch_bounds__(256, 2) void gemm_mma(
    const float* __restrict__ Af, const float* __restrict__ Bf,
    const float* __restrict__ bias, float* __restrict__ Cout)
{
    extern __shared__ __align__(16) float sm[];
    gemm_core<0>(Af, Bf, bias, Cout, blockIdx.x, blockIdx.y, sm);
}

// Fused QKV GEMM: grid.y in [0,9): matrix = y/3, n_ct = y%3
__global__ __launch_bounds__(256, 2) void gemm_qkv(
    const float* __restrict__ Xf,
    const float* __restrict__ wqT, const float* __restrict__ wkT,
    const float* __restrict__ wvT,
    float* __restrict__ qO, float* __restrict__ kO, float* __restrict__ vO)
{
    extern __shared__ __align__(16) float sm[];
    const int mat  = blockIdx.y / 3;
    const int n_ct = blockIdx.y % 3;
    if (mat == 0)      gemm_core<1>(Xf, wqT, nullptr, qO, blockIdx.x, n_ct, sm);
    else if (mat == 1) gemm_core<2>(Xf, wkT, nullptr, kO, blockIdx.x, n_ct, sm);
    else               gemm_core<3>(Xf, wvT, nullptr, vO, blockIdx.x, n_ct, sm);
}

// ===========================================================================
// Tensor-core causal flash attention v4 — 64-row query tile, 128 threads,
// DOUBLE-BUFFERED K/V (prefetch overlaps compute), one barrier per kb.
//   grid = (T/64, H, B). SMEM: Q | K0 | K1 | V0 | V1 | P = 96 KB.
// ===========================================================================
#define ATILE_F 4096
#define ATTN_SMEM (6 * ATILE_F * (int)sizeof(float))

__global__ __launch_bounds__(128, 2) void attn_mma(
    const float* __restrict__ Qf, const float* __restrict__ Kf,
    const float* __restrict__ Vf, float* __restrict__ O)
{
    extern __shared__ __align__(16) float sm[];
    // layout: Qs | K0 | K1 | V0 | V1 | Ps
    float* Qs = sm;
    float* Ps = sm + 5 * ATILE_F;

    const int qb  = blockIdx.x;
    const int h   = blockIdx.y;
    const int b   = blockIdx.z;
    const int tid = threadIdx.x;
    const int wid = tid >> 5, lane = tid & 31;
    const int gid = lane >> 2, tig = lane & 3;
    const int mrow = wid * 16 + gid;

    const int bh = b * HH + h;
    const uint32_t smb = smem_u32(sm);
    const uint32_t dQ = smb + tid * 16;

    // Q tile (A-frag) — load once
    {
        const float* src = Qf + ((long)((bh << 2) + qb) << 12) + tid * 4;
#pragma unroll
        for (int i = 0; i < 8; i++) cp16(dQ + i * 2048, src + i * 512);
        CP_COMMIT();
    }
    // K/V tile kb = 0 -> buffer 0
    {
        const float* sk = Kf + ((long)(bh << 2) << 12) + tid * 4;
        const float* sv = Vf + ((long)(bh << 2) << 12) + tid * 4;
        const uint32_t dK0 = smb + 1 * ATILE_F * 4 + tid * 16;
        const uint32_t dV0 = smb + 3 * ATILE_F * 4 + tid * 16;
#pragma unroll
        for (int i = 0; i < 8; i++) {
            cp16(dK0 + i * 2048, sk + i * 512);
            cp16(dV0 + i * 2048, sv + i * 512);
        }
        CP_COMMIT();
    }

    float o[8][4];
#pragma unroll
    for (int nt = 0; nt < 8; nt++)
#pragma unroll
        for (int r = 0; r < 4; r++) o[nt][r] = 0.0f;
    float m0 = -1e30f, m8 = -1e30f, l0 = 0.0f, l8 = 0.0f;

    for (int kb = 0; kb <= qb; kb++) {
        const int buf = kb & 1;
        CP_WAIT0();            // buffer `buf` loaded
        __syncthreads();       // all warps past previous compute on buf

        // prefetch kb+1 into the other buffer — overlaps this compute phase
        if (kb < qb) {
            const int nb = buf ^ 1;
            const float* sk = Kf + ((long)((bh << 2) + kb + 1) << 12) + tid * 4;
            const float* sv = Vf + ((long)((bh << 2) + kb + 1) << 12) + tid * 4;
            const uint32_t dK = smb + (1 + nb) * ATILE_F * 4 + tid * 16;
            const uint32_t dV = smb + (3 + nb) * ATILE_F * 4 + tid * 16;
#pragma unroll
            for (int i = 0; i < 8; i++) {
                cp16(dK + i * 2048, sk + i * 512);
                cp16(dV + i * 2048, sv + i * 512);
            }
        }
        CP_COMMIT();

        const float* Ks = sm + (1 + buf) * ATILE_F;
        const float* Vs = sm + (3 + buf) * ATILE_F;

        // ---- S = Q K^T ----
        uint4 aq[8];
#pragma unroll
        for (int ks = 0; ks < 8; ks++)
            aq[ks] = *(const uint4*)(Qs + (((wid << 3) + ks) << 7) + lane * 4);

        float s[8][4];
#pragma unroll
        for (int nt = 0; nt < 8; nt++)
#pragma unroll
            for (int r = 0; r < 4; r++) s[nt][r] = 0.0f;

#pragma unroll
        for (int kp = 0; kp < 4; kp++) {
#pragma unroll
            for (int nt = 0; nt < 8; nt++) {
                uint4 bv = *(const uint4*)(Ks + (((nt << 2) + kp) << 7) + lane * 4);
                uint32_t b2[2];
                b2[0] = bv.x; b2[1] = bv.y;
                mma_tf32(s[nt], (const uint32_t*)&aq[2 * kp], b2);
                b2[0] = bv.z; b2[1] = bv.w;
                mma_tf32(s[nt], (const uint32_t*)&aq[2 * kp + 1], b2);
            }
        }

        // ---- scale + causal mask + online softmax ----
        const bool diag = (kb == qb);
        const float scale = 0.125f;
        float rmax0 = -1e30f, rmax8 = -1e30f;
#pragma unroll
        for (int nt = 0; nt < 8; nt++) {
            const int c0 = nt * 8 + 2 * tig;
#pragma unroll
            for (int r = 0; r < 4; r++) {
                const int col = c0 + (r & 1);
                const int row = mrow + ((r >> 1) << 3);
                float v = s[nt][r] * scale;
                if (diag && col > row) v = -1e30f;
                s[nt][r] = v;
                if (r < 2) rmax0 = fmaxf(rmax0, v);
                else       rmax8 = fmaxf(rmax8, v);
            }
        }
        rmax0 = fmaxf(rmax0, __shfl_xor_sync(0xffffffffu, rmax0, 1));
        rmax0 = fmaxf(rmax0, __shfl_xor_sync(0xffffffffu, rmax0, 2));
        rmax8 = fmaxf(rmax8, __shfl_xor_sync(0xffffffffu, rmax8, 1));
        rmax8 = fmaxf(rmax8, __shfl_xor_sync(0xffffffffu, rmax8, 2));

        const float mn0 = fmaxf(m0, rmax0);
        const float mn8 = fmaxf(m8, rmax8);
        const float corr0 = __expf(m0 - mn0);
        const float corr8 = __expf(m8 - mn8);
        m0 = mn0; m8 = mn8;

        float ls0 = 0.0f, ls8 = 0.0f;
#pragma unroll
        for (int nt = 0; nt < 8; nt++) {
            float p0 = __expf(s[nt][0] - mn0);
            float p1 = __expf(s[nt][1] - mn0);
            float p2 = __expf(s[nt][2] - mn8);
            float p3 = __expf(s[nt][3] - mn8);
            s[nt][0] = p0; s[nt][1] = p1; s[nt][2] = p2; s[nt][3] = p3;
            ls0 += p0 + p1;
            ls8 += p2 + p3;
        }
        ls0 += __shfl_xor_sync(0xffffffffu, ls0, 1);
        ls0 += __shfl_xor_sync(0xffffffffu, ls0, 2);
        ls8 += __shfl_xor_sync(0xffffffffu, ls8, 1);
        ls8 += __shfl_xor_sync(0xffffffffu, ls8, 2);

        l0 = l0 * corr0 + ls0;
        l8 = l8 * corr8 + ls8;
#pragma unroll
        for (int nt = 0; nt < 8; nt++) {
            o[nt][0] *= corr0; o[nt][1] *= corr0;
            o[nt][2] *= corr8; o[nt][3] *= corr8;
        }

        // ---- P -> SMEM in A-frag order (warp-private rows) ----
#pragma unroll
        for (int nt = 0; nt < 8; nt++) {
            const int k = nt * 8 + 2 * tig;
            Ps[afrag64(mrow,     k)]     = tf32r(s[nt][0]);
            Ps[afrag64(mrow,     k + 1)] = tf32r(s[nt][1]);
            Ps[afrag64(mrow + 8, k)]     = tf32r(s[nt][2]);
            Ps[afrag64(mrow + 8, k + 1)] = tf32r(s[nt][3]);
        }
        __syncwarp();

        // ---- O += P V ----
        uint4 ap[8];
#pragma unroll
        for (int ks = 0; ks < 8; ks++)
            ap[ks] = *(const uint4*)(Ps + (((wid << 3) + ks) << 7) + lane * 4);
#pragma unroll
        for (int kp = 0; kp < 4; kp++) {
#pragma unroll
            for (int nt = 0; nt < 8; nt++) {
                uint4 bv = *(const uint4*)(Vs + (((nt << 2) + kp) << 7) + lane * 4);
                uint32_t b2[2];
                b2[0] = bv.x; b2[1] = bv.y;
                mma_tf32(o[nt], (const uint32_t*)&ap[2 * kp], b2);
                b2[0] = bv.z; b2[1] = bv.w;
                mma_tf32(o[nt], (const uint32_t*)&ap[2 * kp + 1], b2);
            }
        }
        // no trailing barrier: next iteration's top barrier fences buffer reuse
    }

    // Epilogue: fragment-packed + tf32-rounded A operand for proj GEMM
    const float inv0 = 1.0f / l0;
    const float inv8 = 1.0f / l8;
    const int rowg = b * TT + qb * 64 + mrow;
#pragma unroll
    for (int nt = 0; nt < 8; nt++) {
        const int colg = h * 64 + nt * 8 + 2 * tig;
        O[afrag_off(rowg,     colg)]     = tf32r(o[nt][0] * inv0);
        O[afrag_off(rowg,     colg + 1)] = tf32r(o[nt][1] * inv0);
        O[afrag_off(rowg + 8, colg)]     = tf32r(o[nt][2] * inv8);
        O[afrag_off(rowg + 8, colg + 1)] = tf32r(o[nt][3] * inv8);
    }
}

// ===========================================================================
extern "C" void kernel_launch(void* const* d_in, const int* in_sizes, int n_in,
                              void* d_out, int out_size)
{
    const float* x  = (const float*)d_in[0];
    const float* wq = (const float*)d_in[1];
    const float* wk = (const float*)d_in[2];
    const float* wv = (const float*)d_in[3];
    const float* wp = (const float*)d_in[4];
    const float* bp = (const float*)d_in[5];
    float* out = (float*)d_out;

    float *xf, *qp, *kp, *vp, *ap, *wqT, *wkT, *wvT, *wpT;
    cudaGetSymbolAddress((void**)&xf,  g_xf);
    cudaGetSymbolAddress((void**)&qp,  g_q);
    cudaGetSymbolAddress((void**)&kp,  g_k);
    cudaGetSymbolAddress((void**)&vp,  g_v);
    cudaGetSymbolAddress((void**)&ap,  g_attn);
    cudaGetSymbolAddress((void**)&wqT, g_wqT);
    cudaGetSymbolAddress((void**)&wkT, g_wkT);
    cudaGetSymbolAddress((void**)&wvT, g_wvT);
    cudaGetSymbolAddress((void**)&wpT, g_wpT);

    transpose_w<<<(CC * CC + 255) / 256, 256>>>(wq, wk, wv, wp, wqT, wkT, wvT, wpT);
    pack_a<<<(NTOK * CC / 4 + 255) / 256, 256>>>(x, xf);

    cudaFuncSetAttribute(gemm_qkv,
                         cudaFuncAttributeMaxDynamicSharedMemorySize, GEMM_SMEM);
    cudaFuncSetAttribute(gemm_mma,
                         cudaFuncAttributeMaxDynamicSharedMemorySize, GEMM_SMEM);
    gemm_qkv<<<dim3(NTOK / 128, 9), 256, GEMM_SMEM>>>(xf, wqT, wkT, wvT, qp, kp, vp);

    cudaFuncSetAttribute(attn_mma,
                         cudaFuncAttributeMaxDynamicSharedMemorySize, ATTN_SMEM);
    attn_mma<<<dim3(TT / 64, HH, BB), 128, ATTN_SMEM>>>(qp, kp, vp, ap);

    gemm_mma<<<dim3(NTOK / 128, CC / 128), 256, GEMM_SMEM>>>(ap, wpT, bp, out);
}

// round 12
// speedup vs baseline: 1.4936x; 1.0321x over previous
#include <cuda_runtime.h>
#include <cstdint>

// Problem constants
#define BB 128
#define TT 256
#define CC 384
#define HH 6
#define DD 64
#define NTOK (BB * TT)   // 32768
#define KTILE 32
#define NCHUNK (CC / KTILE)     // 12

// Scratch (static device globals — no dynamic allocation allowed)
__device__ float g_xf[NTOK * CC];      // x, fragment-packed A operand (GEMM)
__device__ float g_q[NTOK * CC];       // A-frag 64x64 tiles per (b,h,qb)
__device__ float g_k[NTOK * CC];       // B-frag 64x64 tiles per (b,h,kb)
__device__ float g_v[NTOK * CC];       // B-frag (n=d,k=key) tiles
__device__ float g_attn[NTOK * CC];    // fragment-packed A operand (GEMM)
__device__ float g_wqT[CC * CC];       // fragment-packed B operands (GEMM)
__device__ float g_wkT[CC * CC];
__device__ float g_wvT[CC * CC];
__device__ float g_wpT[CC * CC];

// ---------------------------------------------------------------------------
__device__ __forceinline__ float tf32r(float x) {
    uint32_t o;
    asm("cvt.rna.tf32.f32 %0, %1;" : "=r"(o) : "f"(x));
    return __uint_as_float(o);
}

__device__ __forceinline__ void mma_tf32(float* c, const uint32_t* a,
                                         const uint32_t* b) {
    asm volatile(
        "mma.sync.aligned.m16n8k8.row.col.f32.tf32.tf32.f32 "
        "{%0,%1,%2,%3}, {%4,%5,%6,%7}, {%8,%9}, {%0,%1,%2,%3};"
        : "+f"(c[0]), "+f"(c[1]), "+f"(c[2]), "+f"(c[3])
        : "r"(a[0]), "r"(a[1]), "r"(a[2]), "r"(a[3]), "r"(b[0]), "r"(b[1]));
}

__device__ __forceinline__ uint32_t smem_u32(const void* p) {
    uint32_t a;
    asm("{ .reg .u64 t; cvta.to.shared.u64 t, %1; cvt.u32.u64 %0, t; }"
        : "=r"(a) : "l"(p));
    return a;
}

__device__ __forceinline__ void cp16(uint32_t dst, const void* src) {
    asm volatile("cp.async.cg.shared.global [%0], [%1], 16;"
                 :: "r"(dst), "l"(src));
}
#define CP_COMMIT() asm volatile("cp.async.commit_group;" ::: "memory")
#define CP_WAIT1()  asm volatile("cp.async.wait_group 1;" ::: "memory")
#define CP_WAIT0()  asm volatile("cp.async.wait_group 0;" ::: "memory")

// ---------------------------------------------------------------------------
// GEMM fragment-packed layouts (per 128x32 block of 4096 floats)
__device__ __forceinline__ int afrag_off(int m, int k) {
    return (((m >> 7) * NCHUNK + (k >> 5)) << 12)
         + (((((m >> 4) & 7) << 2) + ((k >> 3) & 3)) << 7)
         + ((((m & 7) << 2) + (k & 3)) << 2)
         + ((m >> 3) & 1) + (((k >> 2) & 1) << 1);
}
__device__ __forceinline__ int bfrag_off(int n, int k) {
    return (((n >> 7) * NCHUNK + (k >> 5)) << 12)
         + (((((n >> 3) & 15) << 1) + ((k >> 4) & 1)) << 7)
         + ((((n & 7) << 2) + (k & 3)) << 2)
         + (((k >> 3) & 1) << 1) + ((k >> 2) & 1);
}
// Attention fragment layouts (per 64x64 tile of 4096 floats)
__device__ __forceinline__ int afrag64(int m, int k) {
    return ((((m >> 4) << 3) + (k >> 3)) << 7)
         + ((((m & 7) << 2) + (k & 3)) << 2)
         + ((m >> 3) & 1) + (((k >> 2) & 1) << 1);
}
__device__ __forceinline__ int bfrag64(int n, int k) {
    return ((((n >> 3) << 2) + (k >> 4)) << 7)
         + ((((n & 7) << 2) + (k & 3)) << 2)
         + (((k >> 3) & 1) << 1) + ((k >> 2) & 1);
}

// ===========================================================================
// Pack x into fragment-order A operand (tf32-rounded).
// ===========================================================================
__global__ __launch_bounds__(256) void pack_a(const float* __restrict__ X,
                                              float* __restrict__ Xf)
{
    int i4 = blockIdx.x * 256 + threadIdx.x;
    if (i4 >= NTOK * CC / 4) return;
    int m = i4 / (CC / 4);
    int k = (i4 - m * (CC / 4)) * 4;
    float4 v = ((const float4*)X)[i4];
    int base = afrag_off(m, k);
    Xf[base + 0]  = tf32r(v.x);
    Xf[base + 4]  = tf32r(v.y);
    Xf[base + 8]  = tf32r(v.z);
    Xf[base + 12] = tf32r(v.w);
}

// ===========================================================================
// Weights -> fragment-packed B operands (tf32-rounded).
// ===========================================================================
__global__ __launch_bounds__(256) void transpose_w(
    const float* __restrict__ wq, const float* __restrict__ wk,
    const float* __restrict__ wv, const float* __restrict__ wp,
    float* __restrict__ qT, float* __restrict__ kT,
    float* __restrict__ vT, float* __restrict__ pT)
{
    int idx = blockIdx.x * 256 + threadIdx.x;
    if (idx >= CC * CC) return;
    int n = idx / CC, k = idx - n * CC;
    int h = n >> 6, d = n & 63;
    int src = (h * CC + k) * DD + d;
    int off = bfrag_off(n, k);
    qT[off] = tf32r(wq[src]);
    kT[off] = tf32r(wk[src]);
    vT[off] = tf32r(wv[src]);
    pT[off] = tf32r(wp[k * CC + n]);
}

// ===========================================================================
// Tensor-core tf32 GEMM v4: 4 warps, warp tile 64x64 (2m x 2n), CTA 128x128.
//   cp.async 3-stage, one __syncthreads per chunk, fragment-packed gmem.
//   Per warp-chunk: 16 A-frag + 16 B-frag LDS.128 feed 128 HMMA.
//   MODE 0: row-major C + bias; MODE 1/2/3: Q/K/V attention-fragment tiles.
// ===========================================================================
#define STGF 4096
#define GEMM_SMEM (6 * STGF * (int)sizeof(float))   // 98304 B

template <int MODE>
__device__ __forceinline__ void gemm_core(
    const float* __restrict__ Af, const float* __restrict__ Bf,
    const float* __restrict__ bias, float* __restrict__ Cout,
    int m_ct, int n_ct, float* sm)
{
    const int tid = threadIdx.x;
    const int wid = tid >> 5, lane = tid & 31;
    const int gid = lane >> 2, tig = lane & 3;
    const int warp_m = wid & 1;      // 2 x 64 rows
    const int warp_n = wid >> 1;     // 2 x 64 cols

    const uint32_t smb = smem_u32(sm);
    const float* Asrc = Af + ((long)m_ct * NCHUNK << 12) + tid * 4;
    const float* Bsrc = Bf + ((long)n_ct * NCHUNK << 12) + tid * 4;
    const uint32_t dA = smb + tid * 16;
    const uint32_t dB = smb + 3 * STGF * 4 + tid * 16;

    // one stage = 4096 floats; 128 threads x 8 cp16 = full stage
    // prologue: chunks 0,1 -> stages 0,1
#pragma unroll
    for (int s = 0; s < 2; s++) {
#pragma unroll
        for (int i = 0; i < 8; i++) {
            cp16(dA + s * (STGF * 4) + i * 2048, Asrc + s * STGF + i * 512);
            cp16(dB + s * (STGF * 4) + i * 2048, Bsrc + s * STGF + i * 512);
        }
        CP_COMMIT();
    }

    float acc[4][8][4];
#pragma unroll
    for (int i = 0; i < 4; i++)
#pragma unroll
        for (int j = 0; j < 8; j++)
#pragma unroll
            for (int r = 0; r < 4; r++) acc[i][j][r] = 0.0f;

    for (int c = 0; c < NCHUNK; c++) {
        const int s = c - (c / 3) * 3;     // c % 3
        CP_WAIT1();                        // chunk c landed (c+1 may fly)
        __syncthreads();                   // fences readers of stage (c+2)%3

        if (c + 2 < NCHUNK) {              // prefetch chunk c+2
            const int sp = (c + 2) - ((c + 2) / 3) * 3;
#pragma unroll
            for (int i = 0; i < 8; i++) {
                cp16(dA + sp * (STGF * 4) + i * 2048,
                     Asrc + (c + 2) * STGF + i * 512);
                cp16(dB + sp * (STGF * 4) + i * 2048,
                     Bsrc + (c + 2) * STGF + i * 512);
            }
        }
        CP_COMMIT();

        const float* As = sm + s * STGF;
        const float* Bs = sm + (3 + s) * STGF;

#pragma unroll
        for (int kp = 0; kp < 2; kp++) {
            // A fragments for both ks of this pair: 8 LDS.128
            uint4 afv[4][2];
#pragma unroll
            for (int mt = 0; mt < 4; mt++) {
#pragma unroll
                for (int hf = 0; hf < 2; hf++)
                    afv[mt][hf] = *(const uint4*)(As +
                        (((warp_m * 4 + mt) * 4 + kp * 2 + hf) << 7) + lane * 4);
            }
#pragma unroll
            for (int nt = 0; nt < 8; nt++) {
                uint4 bv = *(const uint4*)(Bs +
                    (((warp_n * 8 + nt) * 2 + kp) << 7) + lane * 4);
                uint32_t b2[2];
#pragma unroll
                for (int mt = 0; mt < 4; mt++) {
                    b2[0] = bv.x; b2[1] = bv.y;
                    mma_tf32(acc[mt][nt], (const uint32_t*)&afv[mt][0], b2);
                    b2[0] = bv.z; b2[1] = bv.w;
                    mma_tf32(acc[mt][nt], (const uint32_t*)&afv[mt][1], b2);
                }
            }
        }
    }

#pragma unroll
    for (int mt = 0; mt < 4; mt++) {
#pragma unroll
        for (int nt = 0; nt < 8; nt++) {
            const int n = n_ct * 128 + warp_n * 64 + nt * 8 + 2 * tig;
            const int m = m_ct * 128 + warp_m * 64 + mt * 16 + gid;
            const float c0 = acc[mt][nt][0], c1 = acc[mt][nt][1];
            const float c2 = acc[mt][nt][2], c3 = acc[mt][nt][3];
            if (MODE == 0) {
                float bx = bias ? bias[n] : 0.0f;
                float by = bias ? bias[n + 1] : 0.0f;
                *(float2*)(Cout + (long)m * CC + n) = make_float2(c0 + bx, c1 + by);
                *(float2*)(Cout + (long)(m + 8) * CC + n) = make_float2(c2 + bx, c3 + by);
            } else {
                const int h = n >> 6, d = n & 63;
                const int b = m >> 8, tl = m & 255;
                const int qb = tl >> 6, ml = tl & 63;
                float* dst = Cout + ((long)(((b * HH + h) << 2) + qb) << 12);
                if (MODE == 1) {            // Q: A-frag(m=token, k=d)
                    dst[afrag64(ml,     d)]     = tf32r(c0);
                    dst[afrag64(ml,     d + 1)] = tf32r(c1);
                    dst[afrag64(ml + 8, d)]     = tf32r(c2);
                    dst[afrag64(ml + 8, d + 1)] = tf32r(c3);
                } else if (MODE == 2) {     // K: B-frag(n=token, k=d)
                    dst[bfrag64(ml,     d)]     = tf32r(c0);
                    dst[bfrag64(ml,     d + 1)] = tf32r(c1);
                    dst[bfrag64(ml + 8, d)]     = tf32r(c2);
                    dst[bfrag64(ml + 8, d + 1)] = tf32r(c3);
                } else {                    // V: B-frag(n=d, k=token)
                    dst[bfrag64(d,     ml)]     = tf32r(c0);
                    dst[bfrag64(d + 1, ml)]     = tf32r(c1);
                    dst[bfrag64(d,     ml + 8)] = tf32r(c2);
                    dst[bfrag64(d + 1, ml + 8)] = tf32r(c3);
                }
            }
        }
    }
}

// Output-projection GEMM (with bias, final fp32 out)
__global__ __launch_bounds__(128, 2) void gemm_mma(
    const float* __restrict__ Af, const float* __restrict__ Bf,
    const float* __restrict__ bias, float* __restrict__ Cout)
{
    extern __shared__ __align__(16) float sm[];
    gemm_core<0>(Af, Bf, bias, Cout, blockIdx.x, blockIdx.y, sm);
}

// Fused QKV GEMM: grid.y in [0,9): matrix = y/3, n_ct = y%3
__global__ __launch_bounds__(128, 2) void gemm_qkv(
    const float* __restrict__ Xf,
    const float* __restrict__ wqT, const float* __restrict__ wkT,
    const float* __restrict__ wvT,
    float* __restrict__ qO, float* __restrict__ kO, float* __restrict__ vO)
{
    extern __shared__ __align__(16) float sm[];
    const int mat  = blockIdx.y / 3;
    const int n_ct = blockIdx.y % 3;
    if (mat == 0)      gemm_core<1>(Xf, wqT, nullptr, qO, blockIdx.x, n_ct, sm);
    else if (mat == 1) gemm_core<2>(Xf, wkT, nullptr, kO, blockIdx.x, n_ct, sm);
    else               gemm_core<3>(Xf, wvT, nullptr, vO, blockIdx.x, n_ct, sm);
}

// ===========================================================================
// Tensor-core causal flash attention v4 — 64-row query tile, 128 threads,
// DOUBLE-BUFFERED K/V (prefetch overlaps compute), one barrier per kb.
//   grid = (T/64, H, B). SMEM: Q | K0 | K1 | V0 | V1 | P = 96 KB.
// ===========================================================================
#define ATILE_F 4096
#define ATTN_SMEM (6 * ATILE_F * (int)sizeof(float))

__global__ __launch_bounds__(128, 2) void attn_mma(
    const float* __restrict__ Qf, const float* __restrict__ Kf,
    const float* __restrict__ Vf, float* __restrict__ O)
{
    extern __shared__ __align__(16) float sm[];
    // layout: Qs | K0 | K1 | V0 | V1 | Ps
    float* Qs = sm;
    float* Ps = sm + 5 * ATILE_F;

    const int qb  = blockIdx.x;
    const int h   = blockIdx.y;
    const int b   = blockIdx.z;
    const int tid = threadIdx.x;
    const int wid = tid >> 5, lane = tid & 31;
    const int gid = lane >> 2, tig = lane & 3;
    const int mrow = wid * 16 + gid;

    const int bh = b * HH + h;
    const uint32_t smb = smem_u32(sm);
    const uint32_t dQ = smb + tid * 16;

    // Q tile (A-frag) — load once
    {
        const float* src = Qf + ((long)((bh << 2) + qb) << 12) + tid * 4;
#pragma unroll
        for (int i = 0; i < 8; i++) cp16(dQ + i * 2048, src + i * 512);
        CP_COMMIT();
    }
    // K/V tile kb = 0 -> buffer 0
    {
        const float* sk = Kf + ((long)(bh << 2) << 12) + tid * 4;
        const float* sv = Vf + ((long)(bh << 2) << 12) + tid * 4;
        const uint32_t dK0 = smb + 1 * ATILE_F * 4 + tid * 16;
        const uint32_t dV0 = smb + 3 * ATILE_F * 4 + tid * 16;
#pragma unroll
        for (int i = 0; i < 8; i++) {
            cp16(dK0 + i * 2048, sk + i * 512);
            cp16(dV0 + i * 2048, sv + i * 512);
        }
        CP_COMMIT();
    }

    float o[8][4];
#pragma unroll
    for (int nt = 0; nt < 8; nt++)
#pragma unroll
        for (int r = 0; r < 4; r++) o[nt][r] = 0.0f;
    float m0 = -1e30f, m8 = -1e30f, l0 = 0.0f, l8 = 0.0f;

    for (int kb = 0; kb <= qb; kb++) {
        const int buf = kb & 1;
        CP_WAIT0();            // buffer `buf` loaded
        __syncthreads();       // all warps past previous compute on buf

        // prefetch kb+1 into the other buffer — overlaps this compute phase
        if (kb < qb) {
            const int nb = buf ^ 1;
            const float* sk = Kf + ((long)((bh << 2) + kb + 1) << 12) + tid * 4;
            const float* sv = Vf + ((long)((bh << 2) + kb + 1) << 12) + tid * 4;
            const uint32_t dK = smb + (1 + nb) * ATILE_F * 4 + tid * 16;
            const uint32_t dV = smb + (3 + nb) * ATILE_F * 4 + tid * 16;
#pragma unroll
            for (int i = 0; i < 8; i++) {
                cp16(dK + i * 2048, sk + i * 512);
                cp16(dV + i * 2048, sv + i * 512);
            }
        }
        CP_COMMIT();

        const float* Ks = sm + (1 + buf) * ATILE_F;
        const float* Vs = sm + (3 + buf) * ATILE_F;

        // ---- S = Q K^T ----
        uint4 aq[8];
#pragma unroll
        for (int ks = 0; ks < 8; ks++)
            aq[ks] = *(const uint4*)(Qs + (((wid << 3) + ks) << 7) + lane * 4);

        float s[8][4];
#pragma unroll
        for (int nt = 0; nt < 8; nt++)
#pragma unroll
            for (int r = 0; r < 4; r++) s[nt][r] = 0.0f;

#pragma unroll
        for (int kp = 0; kp < 4; kp++) {
#pragma unroll
            for (int nt = 0; nt < 8; nt++) {
                uint4 bv = *(const uint4*)(Ks + (((nt << 2) + kp) << 7) + lane * 4);
                uint32_t b2[2];
                b2[0] = bv.x; b2[1] = bv.y;
                mma_tf32(s[nt], (const uint32_t*)&aq[2 * kp], b2);
                b2[0] = bv.z; b2[1] = bv.w;
                mma_tf32(s[nt], (const uint32_t*)&aq[2 * kp + 1], b2);
            }
        }

        // ---- scale + causal mask + online softmax ----
        const bool diag = (kb == qb);
        const float scale = 0.125f;
        float rmax0 = -1e30f, rmax8 = -1e30f;
#pragma unroll
        for (int nt = 0; nt < 8; nt++) {
            const int c0 = nt * 8 + 2 * tig;
#pragma unroll
            for (int r = 0; r < 4; r++) {
                const int col = c0 + (r & 1);
                const int row = mrow + ((r >> 1) << 3);
                float v = s[nt][r] * scale;
                if (diag && col > row) v = -1e30f;
                s[nt][r] = v;
                if (r < 2) rmax0 = fmaxf(rmax0, v);
                else       rmax8 = fmaxf(rmax8, v);
            }
        }
        rmax0 = fmaxf(rmax0, __shfl_xor_sync(0xffffffffu, rmax0, 1));
        rmax0 = fmaxf(rmax0, __shfl_xor_sync(0xffffffffu, rmax0, 2));
        rmax8 = fmaxf(rmax8, __shfl_xor_sync(0xffffffffu, rmax8, 1));
        rmax8 = fmaxf(rmax8, __shfl_xor_sync(0xffffffffu, rmax8, 2));

        const float mn0 = fmaxf(m0, rmax0);
        const float mn8 = fmaxf(m8, rmax8);
        const float corr0 = __expf(m0 - mn0);
        const float corr8 = __expf(m8 - mn8);
        m0 = mn0; m8 = mn8;

        float ls0 = 0.0f, ls8 = 0.0f;
#pragma unroll
        for (int nt = 0; nt < 8; nt++) {
            float p0 = __expf(s[nt][0] - mn0);
            float p1 = __expf(s[nt][1] - mn0);
            float p2 = __expf(s[nt][2] - mn8);
            float p3 = __expf(s[nt][3] - mn8);
            s[nt][0] = p0; s[nt][1] = p1; s[nt][2] = p2; s[nt][3] = p3;
            ls0 += p0 + p1;
            ls8 += p2 + p3;
        }
        ls0 += __shfl_xor_sync(0xffffffffu, ls0, 1);
        ls0 += __shfl_xor_sync(0xffffffffu, ls0, 2);
        ls8 += __shfl_xor_sync(0xffffffffu, ls8, 1);
        ls8 += __shfl_xor_sync(0xffffffffu, ls8, 2);

        l0 = l0 * corr0 + ls0;
        l8 = l8 * corr8 + ls8;
#pragma unroll
        for (int nt = 0; nt < 8; nt++) {
            o[nt][0] *= corr0; o[nt][1] *= corr0;
            o[nt][2] *= corr8; o[nt][3] *= corr8;
        }

        // ---- P -> SMEM in A-frag order (warp-private rows) ----
#pragma unroll
        for (int nt = 0; nt < 8; nt++) {
            const int k = nt * 8 + 2 * tig;
            Ps[afrag64(mrow,     k)]     = tf32r(s[nt][0]);
            Ps[afrag64(mrow,     k + 1)] = tf32r(s[nt][1]);
            Ps[afrag64(mrow + 8, k)]     = tf32r(s[nt][2]);
            Ps[afrag64(mrow + 8, k + 1)] = tf32r(s[nt][3]);
        }
        __syncwarp();

        // ---- O += P V ----
        uint4 ap[8];
#pragma unroll
        for (int ks = 0; ks < 8; ks++)
            ap[ks] = *(const uint4*)(Ps + (((wid << 3) + ks) << 7) + lane * 4);
#pragma unroll
        for (int kp = 0; kp < 4; kp++) {
#pragma unroll
            for (int nt = 0; nt < 8; nt++) {
                uint4 bv = *(const uint4*)(Vs + (((nt << 2) + kp) << 7) + lane * 4);
                uint32_t b2[2];
                b2[0] = bv.x; b2[1] = bv.y;
                mma_tf32(o[nt], (const uint32_t*)&ap[2 * kp], b2);
                b2[0] = bv.z; b2[1] = bv.w;
                mma_tf32(o[nt], (const uint32_t*)&ap[2 * kp + 1], b2);
            }
        }
        // no trailing barrier: next iteration's top barrier fences buffer reuse
    }

    // Epilogue: fragment-packed + tf32-rounded A operand for proj GEMM
    const float inv0 = 1.0f / l0;
    const float inv8 = 1.0f / l8;
    const int rowg = b * TT + qb * 64 + mrow;
#pragma unroll
    for (int nt = 0; nt < 8; nt++) {
        const int colg = h * 64 + nt * 8 + 2 * tig;
        O[afrag_off(rowg,     colg)]     = tf32r(o[nt][0] * inv0);
        O[afrag_off(rowg,     colg + 1)] = tf32r(o[nt][1] * inv0);
        O[afrag_off(rowg + 8, colg)]     = tf32r(o[nt][2] * inv8);
        O[afrag_off(rowg + 8, colg + 1)] = tf32r(o[nt][3] * inv8);
    }
}

// ===========================================================================
extern "C" void kernel_launch(void* const* d_in, const int* in_sizes, int n_in,
                              void* d_out, int out_size)
{
    const float* x  = (const float*)d_in[0];
    const float* wq = (const float*)d_in[1];
    const float* wk = (const float*)d_in[2];
    const float* wv = (const float*)d_in[3];
    const float* wp = (const float*)d_in[4];
    const float* bp = (const float*)d_in[5];
    float* out = (float*)d_out;

    float *xf, *qp, *kp, *vp, *ap, *wqT, *wkT, *wvT, *wpT;
    cudaGetSymbolAddress((void**)&xf,  g_xf);
    cudaGetSymbolAddress((void**)&qp,  g_q);
    cudaGetSymbolAddress((void**)&kp,  g_k);
    cudaGetSymbolAddress((void**)&vp,  g_v);
    cudaGetSymbolAddress((void**)&ap,  g_attn);
    cudaGetSymbolAddress((void**)&wqT, g_wqT);
    cudaGetSymbolAddress((void**)&wkT, g_wkT);
    cudaGetSymbolAddress((void**)&wvT, g_wvT);
    cudaGetSymbolAddress((void**)&wpT, g_wpT);

    transpose_w<<<(CC * CC + 255) / 256, 256>>>(wq, wk, wv, wp, wqT, wkT, wvT, wpT);
    pack_a<<<(NTOK * CC / 4 + 255) / 256, 256>>>(x, xf);

    cudaFuncSetAttribute(gemm_qkv,
                         cudaFuncAttributeMaxDynamicSharedMemorySize, GEMM_SMEM);
    cudaFuncSetAttribute(gemm_mma,
                         cudaFuncAttributeMaxDynamicSharedMemorySize, GEMM_SMEM);
    gemm_qkv<<<dim3(NTOK / 128, 9), 128, GEMM_SMEM>>>(xf, wqT, wkT, wvT, qp, kp, vp);

    cudaFuncSetAttribute(attn_mma,
                         cudaFuncAttributeMaxDynamicSharedMemorySize, ATTN_SMEM);
    attn_mma<<<dim3(TT / 64, HH, BB), 128, ATTN_SMEM>>>(qp, kp, vp, ap);

    gemm_mma<<<dim3(NTOK / 128, CC / 128), 128, GEMM_SMEM>>>(ap, wpT, bp, out);
}